// round 1
// baseline (speedup 1.0000x reference)
#include <cuda_runtime.h>
#include <math.h>

// ---------------------------------------------------------------------------
// Problem constants
// ---------------------------------------------------------------------------
#define LNUM 4
#define DDIM 1024
#define HNUM 16
#define HD   64
#define MDIM 4096
#define SLEN 1024
#define BNUM 2
#define NTOK (BNUM*SLEN)        // 2048
#define D3   (3*DDIM)           // 3072
#define EPS  1e-5f

// ---------------------------------------------------------------------------
// Device scratch (no allocations allowed)
// ---------------------------------------------------------------------------
static __device__ float g_qkv [NTOK*D3];     // 24 MB
static __device__ float g_aout[NTOK*DDIM];   // 8 MB
static __device__ float g_proj[NTOK*DDIM];   // 8 MB
static __device__ float g_x   [NTOK*DDIM];   // 8 MB
static __device__ float g_x2  [NTOK*DDIM];   // 8 MB
static __device__ float g_att [NTOK*DDIM];   // 8 MB
static __device__ float g_h   [NTOK*MDIM];   // 32 MB

// ---------------------------------------------------------------------------
// GEMM: C[M,N] = A[M,K] @ Bw[N,K]^T + bias[N]  (+ epilogue)
// EPI: 0 = bias only, 1 = bias + exact GELU, 2 = bias + residual add
// 128x128 tile, BK=8, 256 threads, 8x8 per-thread micro-tile.
// All dims assumed multiples of 128 / 8 (true for this problem).
// ---------------------------------------------------------------------------
template<int EPI>
__global__ __launch_bounds__(256)
void gemm_nt_kernel(const float* __restrict__ A, const float* __restrict__ Bw,
                    const float* __restrict__ bias, const float* __restrict__ Res,
                    float* __restrict__ C, int M, int N, int K)
{
    __shared__ float As[8][128];
    __shared__ float Bs[8][128];

    const int tid = threadIdx.x;
    const int tr  = tid >> 4;           // 0..15
    const int tc  = tid & 15;           // 0..15
    const int m0  = blockIdx.y * 128;
    const int n0  = blockIdx.x * 128;

    const int lrow = tid >> 1;          // 0..127
    const int lcol = (tid & 1) * 4;     // 0 or 4

    const float* Aptr = A  + (size_t)(m0 + lrow) * K + lcol;
    const float* Bptr = Bw + (size_t)(n0 + lrow) * K + lcol;

    float acc[8][8];
    #pragma unroll
    for (int i = 0; i < 8; i++)
        #pragma unroll
        for (int j = 0; j < 8; j++) acc[i][j] = 0.f;

    for (int k0 = 0; k0 < K; k0 += 8) {
        float4 av = *(const float4*)(Aptr + k0);
        float4 bv = *(const float4*)(Bptr + k0);
        As[lcol+0][lrow] = av.x; As[lcol+1][lrow] = av.y;
        As[lcol+2][lrow] = av.z; As[lcol+3][lrow] = av.w;
        Bs[lcol+0][lrow] = bv.x; Bs[lcol+1][lrow] = bv.y;
        Bs[lcol+2][lrow] = bv.z; Bs[lcol+3][lrow] = bv.w;
        __syncthreads();

        #pragma unroll
        for (int kk = 0; kk < 8; kk++) {
            float4 a0 = *(const float4*)&As[kk][tr*8];
            float4 a1 = *(const float4*)&As[kk][tr*8+4];
            float4 b0 = *(const float4*)&Bs[kk][tc*8];
            float4 b1 = *(const float4*)&Bs[kk][tc*8+4];
            float a[8] = {a0.x,a0.y,a0.z,a0.w,a1.x,a1.y,a1.z,a1.w};
            float b[8] = {b0.x,b0.y,b0.z,b0.w,b1.x,b1.y,b1.z,b1.w};
            #pragma unroll
            for (int i = 0; i < 8; i++)
                #pragma unroll
                for (int j = 0; j < 8; j++)
                    acc[i][j] = fmaf(a[i], b[j], acc[i][j]);
        }
        __syncthreads();
    }

    // Epilogue
    float bvals[8];
    #pragma unroll
    for (int j = 0; j < 8; j++) bvals[j] = bias[n0 + tc*8 + j];

    #pragma unroll
    for (int i = 0; i < 8; i++) {
        const int m = m0 + tr*8 + i;
        float* crow = C + (size_t)m * N + n0 + tc*8;
        const float* rrow = (EPI == 2) ? (Res + (size_t)m * N + n0 + tc*8) : nullptr;
        float v[8];
        #pragma unroll
        for (int j = 0; j < 8; j++) {
            float t = acc[i][j] + bvals[j];
            if (EPI == 1) t = 0.5f * t * (1.f + erff(t * 0.70710678118654752f));
            if (EPI == 2) t += rrow[j];
            v[j] = t;
        }
        *(float4*)(crow)     = make_float4(v[0], v[1], v[2], v[3]);
        *(float4*)(crow + 4) = make_float4(v[4], v[5], v[6], v[7]);
    }
}

// ---------------------------------------------------------------------------
// Full attention (flash-style, fp32). One block per (b*h, q-tile of 64).
// qkv layout: [N, 3D], q at col h*64, k at 1024+h*64, v at 2048+h*64.
// out: merged heads [N, D].
// Dynamic smem: Qs/Ks (d-major, [64][68]), Vs (key-major [64][68]),
// P [64][68], plus row stats.
// ---------------------------------------------------------------------------
#define ATTN_SMEM_FLOATS (4*64*68 + 3*64)
#define ATTN_SMEM_BYTES  (ATTN_SMEM_FLOATS*4)

__global__ __launch_bounds__(256)
void attn_full_kernel(const float* __restrict__ qkv, float* __restrict__ out)
{
    extern __shared__ float sm[];
    float* Qs   = sm;                 // [d][q] pitch 68
    float* Ks   = Qs + 64*68;         // [d][k] pitch 68
    float* Vs   = Ks + 64*68;         // [k][d] pitch 68
    float* Pm   = Vs + 64*68;         // [q][k] pitch 68
    float* mrow = Pm + 64*68;
    float* lrow = mrow + 64;
    float* srow = lrow + 64;

    const int bh = blockIdx.x;        // 0..31
    const int b  = bh >> 4;
    const int h  = bh & 15;
    const int qt = blockIdx.y;        // 0..15
    const int tid = threadIdx.x;

    const int r   = tid >> 2;         // 0..63 (row for loads)
    const int seg = tid & 3;          // 0..3

    // Load Q tile transposed
    {
        const size_t qbase = (size_t)(b*SLEN + qt*64 + r) * D3 + h*HD;
        #pragma unroll
        for (int it = 0; it < 4; it++) {
            int d0 = (seg*4 + it) * 4;
            float4 v = *(const float4*)(qkv + qbase + d0);
            Qs[(d0+0)*68 + r] = v.x;
            Qs[(d0+1)*68 + r] = v.y;
            Qs[(d0+2)*68 + r] = v.z;
            Qs[(d0+3)*68 + r] = v.w;
        }
    }
    if (tid < 64) { mrow[tid] = -1e30f; lrow[tid] = 0.f; }

    const int q0 = (tid >> 4) * 4;    // 4 query rows owned
    const int c0 = (tid & 15) * 4;    // 4 cols owned (k for scores, d for AV)
    float acc[4][4];
    #pragma unroll
    for (int i = 0; i < 4; i++)
        #pragma unroll
        for (int j = 0; j < 4; j++) acc[i][j] = 0.f;

    for (int kt = 0; kt < 16; kt++) {
        __syncthreads();
        // Load K (transposed) and V (natural)
        {
            const size_t kbase = (size_t)(b*SLEN + kt*64 + r) * D3 + DDIM + h*HD;
            const size_t vbase = kbase + DDIM;
            #pragma unroll
            for (int it = 0; it < 4; it++) {
                int d0 = (seg*4 + it) * 4;
                float4 kv = *(const float4*)(qkv + kbase + d0);
                Ks[(d0+0)*68 + r] = kv.x;
                Ks[(d0+1)*68 + r] = kv.y;
                Ks[(d0+2)*68 + r] = kv.z;
                Ks[(d0+3)*68 + r] = kv.w;
                float4 vv = *(const float4*)(qkv + vbase + d0);
                *(float4*)&Vs[r*68 + d0] = vv;
            }
        }
        __syncthreads();

        // Scores: s[i][j] = sum_d Q[q0+i][d] * K[c0+j][d]
        float s[4][4];
        #pragma unroll
        for (int i = 0; i < 4; i++)
            #pragma unroll
            for (int j = 0; j < 4; j++) s[i][j] = 0.f;
        #pragma unroll 8
        for (int d = 0; d < 64; d++) {
            float a0 = Qs[d*68 + q0+0], a1 = Qs[d*68 + q0+1];
            float a2 = Qs[d*68 + q0+2], a3 = Qs[d*68 + q0+3];
            float e0 = Ks[d*68 + c0+0], e1 = Ks[d*68 + c0+1];
            float e2 = Ks[d*68 + c0+2], e3 = Ks[d*68 + c0+3];
            s[0][0]=fmaf(a0,e0,s[0][0]); s[0][1]=fmaf(a0,e1,s[0][1]);
            s[0][2]=fmaf(a0,e2,s[0][2]); s[0][3]=fmaf(a0,e3,s[0][3]);
            s[1][0]=fmaf(a1,e0,s[1][0]); s[1][1]=fmaf(a1,e1,s[1][1]);
            s[1][2]=fmaf(a1,e2,s[1][2]); s[1][3]=fmaf(a1,e3,s[1][3]);
            s[2][0]=fmaf(a2,e0,s[2][0]); s[2][1]=fmaf(a2,e1,s[2][1]);
            s[2][2]=fmaf(a2,e2,s[2][2]); s[2][3]=fmaf(a2,e3,s[2][3]);
            s[3][0]=fmaf(a3,e0,s[3][0]); s[3][1]=fmaf(a3,e1,s[3][1]);
            s[3][2]=fmaf(a3,e2,s[3][2]); s[3][3]=fmaf(a3,e3,s[3][3]);
        }
        #pragma unroll
        for (int i = 0; i < 4; i++)
            #pragma unroll
            for (int j = 0; j < 4; j++)
                Pm[(q0+i)*68 + c0+j] = s[i][j] * 0.125f;
        __syncthreads();

        // Online softmax per query row (threads 0..63)
        if (tid < 64) {
            float* row = &Pm[tid*68];
            float mold = mrow[tid];
            float mx = mold;
            #pragma unroll 8
            for (int k = 0; k < 64; k++) mx = fmaxf(mx, row[k]);
            float sum = 0.f;
            #pragma unroll 8
            for (int k = 0; k < 64; k++) {
                float e = __expf(row[k] - mx);
                row[k] = e;
                sum += e;
            }
            float sc = __expf(mold - mx);
            lrow[tid] = lrow[tid] * sc + sum;
            mrow[tid] = mx;
            srow[tid] = sc;
        }
        __syncthreads();

        // Rescale accumulators and add P @ V
        #pragma unroll
        for (int i = 0; i < 4; i++) {
            float sc = srow[q0+i];
            #pragma unroll
            for (int j = 0; j < 4; j++) acc[i][j] *= sc;
        }
        #pragma unroll 8
        for (int k = 0; k < 64; k++) {
            float p0 = Pm[(q0+0)*68 + k], p1 = Pm[(q0+1)*68 + k];
            float p2 = Pm[(q0+2)*68 + k], p3 = Pm[(q0+3)*68 + k];
            float v0 = Vs[k*68 + c0+0], v1 = Vs[k*68 + c0+1];
            float v2 = Vs[k*68 + c0+2], v3 = Vs[k*68 + c0+3];
            acc[0][0]=fmaf(p0,v0,acc[0][0]); acc[0][1]=fmaf(p0,v1,acc[0][1]);
            acc[0][2]=fmaf(p0,v2,acc[0][2]); acc[0][3]=fmaf(p0,v3,acc[0][3]);
            acc[1][0]=fmaf(p1,v0,acc[1][0]); acc[1][1]=fmaf(p1,v1,acc[1][1]);
            acc[1][2]=fmaf(p1,v2,acc[1][2]); acc[1][3]=fmaf(p1,v3,acc[1][3]);
            acc[2][0]=fmaf(p2,v0,acc[2][0]); acc[2][1]=fmaf(p2,v1,acc[2][1]);
            acc[2][2]=fmaf(p2,v2,acc[2][2]); acc[2][3]=fmaf(p2,v3,acc[2][3]);
            acc[3][0]=fmaf(p3,v0,acc[3][0]); acc[3][1]=fmaf(p3,v1,acc[3][1]);
            acc[3][2]=fmaf(p3,v2,acc[3][2]); acc[3][3]=fmaf(p3,v3,acc[3][3]);
        }
    }

    // Epilogue: out = acc / l
    #pragma unroll
    for (int i = 0; i < 4; i++) {
        float linv = 1.f / lrow[q0+i];
        const size_t o = (size_t)(b*SLEN + qt*64 + q0+i) * DDIM + h*HD + c0;
        *(float4*)(out + o) = make_float4(acc[i][0]*linv, acc[i][1]*linv,
                                          acc[i][2]*linv, acc[i][3]*linv);
    }
}

// ---------------------------------------------------------------------------
// Banded attention (|i-j| <= 2). One warp per (b,h,i) query.
// Lane handles dims d=lane and d=lane+32.
// ---------------------------------------------------------------------------
__global__ __launch_bounds__(256)
void attn_band_kernel(const float* __restrict__ qkv, float* __restrict__ out)
{
    const int gw   = (blockIdx.x * blockDim.x + threadIdx.x) >> 5;
    const int lane = threadIdx.x & 31;
    const int i = gw & (SLEN-1);
    const int h = (gw >> 10) & (HNUM-1);
    const int b = gw >> 14;

    const size_t qbase = (size_t)(b*SLEN + i) * D3 + h*HD;
    const float q0 = qkv[qbase + lane];
    const float q1 = qkv[qbase + 32 + lane];

    float sc[5];
    int   jc[5];
    #pragma unroll
    for (int jj = 0; jj < 5; jj++) {
        int j = i - 2 + jj;
        bool valid = (j >= 0) && (j < SLEN);
        jc[jj] = valid ? j : i;
        const size_t kb = (size_t)(b*SLEN + jc[jj]) * D3 + DDIM + h*HD;
        float p = q0 * qkv[kb + lane] + q1 * qkv[kb + 32 + lane];
        #pragma unroll
        for (int off = 16; off; off >>= 1) p += __shfl_xor_sync(0xffffffffu, p, off);
        sc[jj] = valid ? p * 0.125f : -1e30f;
    }
    float mx = sc[0];
    #pragma unroll
    for (int jj = 1; jj < 5; jj++) mx = fmaxf(mx, sc[jj]);
    float w[5], sum = 0.f;
    #pragma unroll
    for (int jj = 0; jj < 5; jj++) { w[jj] = __expf(sc[jj] - mx); sum += w[jj]; }
    const float inv = 1.f / sum;

    float o0 = 0.f, o1 = 0.f;
    #pragma unroll
    for (int jj = 0; jj < 5; jj++) {
        const size_t vb = (size_t)(b*SLEN + jc[jj]) * D3 + 2*DDIM + h*HD;
        o0 = fmaf(w[jj], qkv[vb + lane], o0);
        o1 = fmaf(w[jj], qkv[vb + 32 + lane], o1);
    }
    const size_t ob = (size_t)(b*SLEN + i) * DDIM + h*HD;
    out[ob + lane]      = o0 * inv;
    out[ob + 32 + lane] = o1 * inv;
}

// ---------------------------------------------------------------------------
// LayerNorm: out = LN(a + r) * g + b   (r optional). One block per token.
// ---------------------------------------------------------------------------
__global__ __launch_bounds__(256)
void ln_kernel(const float* __restrict__ a, const float* __restrict__ r,
               const float* __restrict__ g, const float* __restrict__ bt,
               float* __restrict__ out)
{
    __shared__ float red[2][8];
    __shared__ float s_mean, s_rstd;
    const int n = blockIdx.x;
    const int tid = threadIdx.x;
    const size_t base = (size_t)n * DDIM + tid * 4;

    float4 va = *(const float4*)(a + base);
    if (r) {
        float4 vr = *(const float4*)(r + base);
        va.x += vr.x; va.y += vr.y; va.z += vr.z; va.w += vr.w;
    }
    float s  = va.x + va.y + va.z + va.w;
    float sq = va.x*va.x + va.y*va.y + va.z*va.z + va.w*va.w;

    #pragma unroll
    for (int off = 16; off; off >>= 1) {
        s  += __shfl_xor_sync(0xffffffffu, s,  off);
        sq += __shfl_xor_sync(0xffffffffu, sq, off);
    }
    const int wid = tid >> 5;
    if ((tid & 31) == 0) { red[0][wid] = s; red[1][wid] = sq; }
    __syncthreads();
    if (tid < 32) {
        float ts  = (tid < 8) ? red[0][tid] : 0.f;
        float tsq = (tid < 8) ? red[1][tid] : 0.f;
        #pragma unroll
        for (int off = 4; off; off >>= 1) {
            ts  += __shfl_xor_sync(0xffffffffu, ts,  off);
            tsq += __shfl_xor_sync(0xffffffffu, tsq, off);
        }
        if (tid == 0) {
            float mean = ts * (1.f / DDIM);
            float var  = tsq * (1.f / DDIM) - mean * mean;
            s_mean = mean;
            s_rstd = rsqrtf(var + EPS);
        }
    }
    __syncthreads();
    const float mean = s_mean, rstd = s_rstd;
    float4 gg = *(const float4*)(g + tid*4);
    float4 bb = *(const float4*)(bt + tid*4);
    float4 o;
    o.x = (va.x - mean) * rstd * gg.x + bb.x;
    o.y = (va.y - mean) * rstd * gg.y + bb.y;
    o.z = (va.z - mean) * rstd * gg.z + bb.z;
    o.w = (va.w - mean) * rstd * gg.w + bb.w;
    *(float4*)(out + base) = o;
}

// ---------------------------------------------------------------------------
// Orchestration
// ---------------------------------------------------------------------------
extern "C" void kernel_launch(void* const* d_in, const int* in_sizes, int n_in,
                              void* d_out, int out_size)
{
    const float* x_in   = (const float*)d_in[0];
    const float* w_in1  = (const float*)d_in[1];
    const float* b_in1  = (const float*)d_in[2];
    const float* w_out1 = (const float*)d_in[3];
    const float* b_out1 = (const float*)d_in[4];
    const float* ln1_g  = (const float*)d_in[5];
    const float* ln1_b  = (const float*)d_in[6];
    const float* w_in2  = (const float*)d_in[7];
    const float* b_in2  = (const float*)d_in[8];
    const float* w_out2 = (const float*)d_in[9];
    const float* b_out2 = (const float*)d_in[10];
    const float* ln2_g  = (const float*)d_in[11];
    const float* ln2_b  = (const float*)d_in[12];
    const float* ffn_w1 = (const float*)d_in[13];
    const float* ffn_b1 = (const float*)d_in[14];
    const float* ffn_w2 = (const float*)d_in[15];
    const float* ffn_b2 = (const float*)d_in[16];
    const float* lnf_g  = (const float*)d_in[17];
    const float* lnf_b  = (const float*)d_in[18];

    float *QKV, *AOUT, *PROJ, *X, *X2, *ATT, *HB;
    cudaGetSymbolAddress((void**)&QKV,  g_qkv);
    cudaGetSymbolAddress((void**)&AOUT, g_aout);
    cudaGetSymbolAddress((void**)&PROJ, g_proj);
    cudaGetSymbolAddress((void**)&X,    g_x);
    cudaGetSymbolAddress((void**)&X2,   g_x2);
    cudaGetSymbolAddress((void**)&ATT,  g_att);
    cudaGetSymbolAddress((void**)&HB,   g_h);

    cudaFuncSetAttribute(attn_full_kernel,
                         cudaFuncAttributeMaxDynamicSharedMemorySize, ATTN_SMEM_BYTES);

    const dim3 blk(256);
    const dim3 g_qkvp(D3/128,  NTOK/128);   // (24,16)
    const dim3 g_out (DDIM/128, NTOK/128);  // (8,16)
    const dim3 g_ffn1(MDIM/128, NTOK/128);  // (32,16)
    const dim3 g_attn(BNUM*HNUM, SLEN/64);  // (32,16)
    const int  g_band = (BNUM*HNUM*SLEN*32) / 256;  // 4096 blocks
    const int  g_ln   = NTOK;

    const float* xcur = x_in;
    for (int l = 0; l < LNUM; l++) {
        const size_t oW3 = (size_t)l * D3 * DDIM;
        const size_t oW1 = (size_t)l * DDIM * DDIM;
        const size_t oWm = (size_t)l * MDIM * DDIM;

        // ---- intra-frame full MHA ----
        gemm_nt_kernel<0><<<g_qkvp, blk>>>(xcur, w_in1 + oW3, b_in1 + (size_t)l*D3,
                                           nullptr, QKV, NTOK, D3, DDIM);
        attn_full_kernel<<<g_attn, blk, ATTN_SMEM_BYTES>>>(QKV, AOUT);
        gemm_nt_kernel<0><<<g_out, blk>>>(AOUT, w_out1 + oW1, b_out1 + (size_t)l*DDIM,
                                          nullptr, PROJ, NTOK, DDIM, DDIM);
        ln_kernel<<<g_ln, blk>>>(PROJ, xcur, ln1_g + (size_t)l*DDIM, ln1_b + (size_t)l*DDIM, X2);

        // ---- inter-frame banded MHA ----
        gemm_nt_kernel<0><<<g_qkvp, blk>>>(X2, w_in2 + oW3, b_in2 + (size_t)l*D3,
                                           nullptr, QKV, NTOK, D3, DDIM);
        attn_band_kernel<<<g_band, blk>>>(QKV, AOUT);
        gemm_nt_kernel<0><<<g_out, blk>>>(AOUT, w_out2 + oW1, b_out2 + (size_t)l*DDIM,
                                          nullptr, PROJ, NTOK, DDIM, DDIM);
        ln_kernel<<<g_ln, blk>>>(PROJ, X2, ln2_g + (size_t)l*DDIM, ln2_b + (size_t)l*DDIM, ATT);

        // ---- FFN ----
        gemm_nt_kernel<1><<<g_ffn1, blk>>>(ATT, ffn_w1 + oWm, ffn_b1 + (size_t)l*MDIM,
                                           nullptr, HB, NTOK, MDIM, DDIM);
        gemm_nt_kernel<2><<<g_out, blk>>>(HB, ffn_w2 + oWm, ffn_b2 + (size_t)l*DDIM,
                                          ATT, X, NTOK, DDIM, MDIM);
        xcur = X;
    }

    ln_kernel<<<g_ln, blk>>>(xcur, nullptr, lnf_g, lnf_b, (float*)d_out);
}

// round 3
// speedup vs baseline: 1.8227x; 1.8227x over previous
#include <cuda_runtime.h>
#include <cuda_bf16.h>
#include <math.h>
#include <stdint.h>

// ---------------------------------------------------------------------------
// Problem constants
// ---------------------------------------------------------------------------
#define LNUM 4
#define DDIM 1024
#define HNUM 16
#define HD   64
#define MDIM 4096
#define SLEN 1024
#define BNUM 2
#define NTOK (BNUM*SLEN)        // 2048
#define D3   (3*DDIM)           // 3072
#define EPS  1e-5f

// Weight split array layout (element offsets)
#define W_IN1_OFF   0u
#define W_OUT1_OFF  12582912u
#define W_IN2_OFF   16777216u
#define W_OUT2_OFF  29360128u
#define FW1_OFF     33554432u
#define FW2_OFF     50331648u
#define WTOTAL      67108864u

// ---------------------------------------------------------------------------
// Device scratch (no allocations allowed)
// ---------------------------------------------------------------------------
static __device__ float g_qkv [NTOK*D3];     // fp32 qkv for attention
static __device__ float g_aout[NTOK*DDIM];
static __device__ float g_proj[NTOK*DDIM];
static __device__ float g_x   [NTOK*DDIM];
static __device__ float g_x2  [NTOK*DDIM];
static __device__ float g_att [NTOK*DDIM];

static __device__ __nv_bfloat16 g_wh[WTOTAL];        // weight hi
static __device__ __nv_bfloat16 g_wl[WTOTAL];        // weight lo
static __device__ __nv_bfloat16 g_p1h[NTOK*DDIM];    // activation split (1024 wide)
static __device__ __nv_bfloat16 g_p1l[NTOK*DDIM];
static __device__ __nv_bfloat16 g_p2h[NTOK*MDIM];    // activation split (4096 wide)
static __device__ __nv_bfloat16 g_p2l[NTOK*MDIM];

// ---------------------------------------------------------------------------
// Helpers
// ---------------------------------------------------------------------------
__device__ __forceinline__ void cp16(uint32_t d, const void* s) {
    asm volatile("cp.async.cg.shared.global [%0], [%1], 16;\n" :: "r"(d), "l"(s));
}
__device__ __forceinline__ void cp_commit() {
    asm volatile("cp.async.commit_group;\n" ::: "memory");
}
__device__ __forceinline__ void ldsm4(uint32_t* r, uint32_t a) {
    asm volatile("ldmatrix.sync.aligned.m8n8.x4.shared.b16 {%0,%1,%2,%3}, [%4];"
        : "=r"(r[0]), "=r"(r[1]), "=r"(r[2]), "=r"(r[3]) : "r"(a));
}
__device__ __forceinline__ void mma16816(float* c, const uint32_t* a,
                                         uint32_t b0, uint32_t b1) {
    asm volatile(
        "mma.sync.aligned.m16n8k16.row.col.f32.bf16.bf16.f32 "
        "{%0,%1,%2,%3},{%4,%5,%6,%7},{%8,%9},{%0,%1,%2,%3};"
        : "+f"(c[0]), "+f"(c[1]), "+f"(c[2]), "+f"(c[3])
        : "r"(a[0]), "r"(a[1]), "r"(a[2]), "r"(a[3]), "r"(b0), "r"(b1));
}
__device__ __forceinline__ uint32_t pack2(__nv_bfloat16 a, __nv_bfloat16 b) {
    __nv_bfloat162 t = __halves2bfloat162(a, b);
    return *reinterpret_cast<uint32_t*>(&t);
}
__device__ __forceinline__ void split1(float v, __nv_bfloat16& h, __nv_bfloat16& l) {
    h = __float2bfloat16(v);
    l = __float2bfloat16(v - __bfloat162float(h));
}

// ---------------------------------------------------------------------------
// fp32 -> (hi,lo) bf16 split kernel. n must be a multiple of 1024.
// ---------------------------------------------------------------------------
__global__ __launch_bounds__(256)
void split_kernel(const float* __restrict__ in, __nv_bfloat16* __restrict__ hi,
                  __nv_bfloat16* __restrict__ lo)
{
    const size_t i = ((size_t)blockIdx.x * 256 + threadIdx.x) * 4;
    float4 v = *(const float4*)(in + i);
    __nv_bfloat16 h0,h1,h2,h3,l0,l1,l2,l3;
    split1(v.x,h0,l0); split1(v.y,h1,l1); split1(v.z,h2,l2); split1(v.w,h3,l3);
    uint2 uh; uh.x = pack2(h0,h1); uh.y = pack2(h2,h3);
    uint2 ul; ul.x = pack2(l0,l1); ul.y = pack2(l2,l3);
    *(uint2*)(hi + i) = uh;
    *(uint2*)(lo + i) = ul;
}

// ---------------------------------------------------------------------------
// bf16x3 tensor-core GEMM: C[M,N] = A[M,K] @ Bw[N,K]^T + bias (+ epilogue)
// A,B given as (hi,lo) bf16 pairs; product = Ah*Bh + Ah*Bl + Al*Bh (fp32 acc).
// Tile 128x128x32, 256 threads, 8 warps (warp tile 64m x 32n), cp.async
// double buffered. EPI: 0=bias, 1=bias+GELU, 2=bias+residual.
// OSPLIT: write hi/lo bf16 outputs. OF32: write fp32 output.
// ---------------------------------------------------------------------------
#define STAGE_ELEMS 16384
#define STAGE_BYTES 32768
#define GSMEM_BYTES (2*STAGE_BYTES)

template<int EPI, bool OSPLIT, bool OF32>
__global__ __launch_bounds__(256)
void gemm_bf3(const __nv_bfloat16* __restrict__ Ah, const __nv_bfloat16* __restrict__ Al,
              const __nv_bfloat16* __restrict__ Bh, const __nv_bfloat16* __restrict__ Bl,
              const float* __restrict__ bias, const float* __restrict__ Res,
              float* __restrict__ C, __nv_bfloat16* __restrict__ Chi,
              __nv_bfloat16* __restrict__ Clo, int M, int N, int K)
{
    extern __shared__ __nv_bfloat16 smbuf[];
    const uint32_t smem_u32 = (uint32_t)__cvta_generic_to_shared(smbuf);

    const int tid = threadIdx.x;
    const int m0 = blockIdx.y * 128;
    const int n0 = blockIdx.x * 128;

    // ---- global->smem mapping (16B chunks) ----
    const int m_ld  = tid & 127;          // row within tile
    const int ko_ld = tid >> 7;           // 0..1 (second chunk at ko+2)
    const uint32_t oC1 = (uint32_t)(((ko_ld    )*128 + m_ld) * 8) * 2;  // bytes
    const uint32_t oC2 = (uint32_t)(((ko_ld + 2)*128 + m_ld) * 8) * 2;

    const __nv_bfloat16* pAh = Ah + (size_t)(m0 + m_ld) * K + ko_ld * 8;
    const __nv_bfloat16* pAl = Al + (size_t)(m0 + m_ld) * K + ko_ld * 8;
    const __nv_bfloat16* pBh = Bh + (size_t)(n0 + m_ld) * K + ko_ld * 8;
    const __nv_bfloat16* pBl = Bl + (size_t)(n0 + m_ld) * K + ko_ld * 8;

    // ---- warp/frag mapping ----
    const int wid  = tid >> 5;
    const int lane = tid & 31;
    const int wm = (wid >> 2) * 64;       // 0 or 64
    const int wn = (wid & 3) * 32;        // 0,32,64,96
    const int a_row = lane & 15;
    const int a_ko  = lane >> 4;                           // 0..1
    const int b_row = (lane & 7) + ((lane & 16) >> 1);     // +8 for upper half
    const int b_ko  = (lane >> 3) & 1;

    const uint32_t aoff = (uint32_t)((a_ko*1024 + (wm + a_row)*8) * 2);
    const uint32_t boff = (uint32_t)((b_ko*1024 + (wn + b_row)*8) * 2);

    float acc[4][4][4];
    #pragma unroll
    for (int i = 0; i < 4; i++)
        #pragma unroll
        for (int j = 0; j < 4; j++)
            #pragma unroll
            for (int e = 0; e < 4; e++) acc[i][j][e] = 0.f;

    const int T = K >> 5;

    // ---- stage loader ----
    auto load_stage = [&](int kt, int s) {
        const uint32_t sb = smem_u32 + s * STAGE_BYTES;
        const size_t gk = (size_t)kt * 32;
        cp16(sb + oC1,          pAh + gk);
        cp16(sb + oC2,          pAh + gk + 16);
        cp16(sb + 8192  + oC1,  pAl + gk);
        cp16(sb + 8192  + oC2,  pAl + gk + 16);
        cp16(sb + 16384 + oC1,  pBh + gk);
        cp16(sb + 16384 + oC2,  pBh + gk + 16);
        cp16(sb + 24576 + oC1,  pBl + gk);
        cp16(sb + 24576 + oC2,  pBl + gk + 16);
        cp_commit();
    };

    load_stage(0, 0);

    for (int kt = 0; kt < T; kt++) {
        const int s = kt & 1;
        if (kt + 1 < T) {
            load_stage(kt + 1, s ^ 1);
            asm volatile("cp.async.wait_group 1;\n" ::: "memory");
        } else {
            asm volatile("cp.async.wait_group 0;\n" ::: "memory");
        }
        __syncthreads();

        const uint32_t sb = smem_u32 + s * STAGE_BYTES;
        #pragma unroll
        for (int ko0 = 0; ko0 < 4; ko0 += 2) {
            uint32_t a_h[4][4], a_l[4][4], b_h[8], b_l[8];
            #pragma unroll
            for (int mf = 0; mf < 4; mf++) {
                const uint32_t ad = sb + aoff + (uint32_t)ko0*2048 + (uint32_t)mf*256;
                ldsm4(a_h[mf], ad);
                ldsm4(a_l[mf], ad + 8192);
            }
            #pragma unroll
            for (int nf2 = 0; nf2 < 2; nf2++) {
                const uint32_t bd = sb + 16384 + boff + (uint32_t)ko0*2048 + (uint32_t)nf2*256;
                ldsm4(&b_h[nf2*4], bd);
                ldsm4(&b_l[nf2*4], bd + 8192);
            }
            #pragma unroll
            for (int mf = 0; mf < 4; mf++)
                #pragma unroll
                for (int nf = 0; nf < 4; nf++) {
                    mma16816(acc[mf][nf], a_h[mf], b_h[nf*2], b_h[nf*2+1]);
                    mma16816(acc[mf][nf], a_h[mf], b_l[nf*2], b_l[nf*2+1]);
                    mma16816(acc[mf][nf], a_l[mf], b_h[nf*2], b_h[nf*2+1]);
                }
        }
        __syncthreads();
    }

    // ---- epilogue ----
    const int er = lane >> 2;
    const int ec = (lane & 3) * 2;
    #pragma unroll
    for (int mf = 0; mf < 4; mf++) {
        #pragma unroll
        for (int nf = 0; nf < 4; nf++) {
            const int m = m0 + wm + mf*16 + er;
            const int n = n0 + wn + nf*8 + ec;
            const float2 bv = *(const float2*)(bias + n);
            #pragma unroll
            for (int half = 0; half < 2; half++) {
                const int mm = m + half*8;
                float t0 = acc[mf][nf][half*2+0] + bv.x;
                float t1 = acc[mf][nf][half*2+1] + bv.y;
                if (EPI == 1) {
                    t0 = 0.5f * t0 * (1.f + erff(t0 * 0.70710678118654752f));
                    t1 = 0.5f * t1 * (1.f + erff(t1 * 0.70710678118654752f));
                }
                if (EPI == 2) {
                    const float2 rv = *(const float2*)(Res + (size_t)mm * N + n);
                    t0 += rv.x; t1 += rv.y;
                }
                if (OF32) {
                    *(float2*)(C + (size_t)mm * N + n) = make_float2(t0, t1);
                }
                if (OSPLIT) {
                    __nv_bfloat16 h0,h1,l0,l1;
                    split1(t0,h0,l0); split1(t1,h1,l1);
                    *(uint32_t*)(Chi + (size_t)mm * N + n) = pack2(h0,h1);
                    *(uint32_t*)(Clo + (size_t)mm * N + n) = pack2(l0,l1);
                }
            }
        }
    }
}

// ---------------------------------------------------------------------------
// Full attention (flash-style, fp32).
// ---------------------------------------------------------------------------
#define ATTN_SMEM_FLOATS (4*64*68 + 3*64)
#define ATTN_SMEM_BYTES  (ATTN_SMEM_FLOATS*4)

__global__ __launch_bounds__(256)
void attn_full_kernel(const float* __restrict__ qkv, float* __restrict__ out)
{
    extern __shared__ float sm[];
    float* Qs   = sm;
    float* Ks   = Qs + 64*68;
    float* Vs   = Ks + 64*68;
    float* Pm   = Vs + 64*68;
    float* mrow = Pm + 64*68;
    float* lrow = mrow + 64;
    float* srow = lrow + 64;

    const int bh = blockIdx.x;
    const int b  = bh >> 4;
    const int h  = bh & 15;
    const int qt = blockIdx.y;
    const int tid = threadIdx.x;

    const int r   = tid >> 2;
    const int seg = tid & 3;

    {
        const size_t qbase = (size_t)(b*SLEN + qt*64 + r) * D3 + h*HD;
        #pragma unroll
        for (int it = 0; it < 4; it++) {
            int d0 = (seg*4 + it) * 4;
            float4 v = *(const float4*)(qkv + qbase + d0);
            Qs[(d0+0)*68 + r] = v.x;
            Qs[(d0+1)*68 + r] = v.y;
            Qs[(d0+2)*68 + r] = v.z;
            Qs[(d0+3)*68 + r] = v.w;
        }
    }
    if (tid < 64) { mrow[tid] = -1e30f; lrow[tid] = 0.f; }

    const int q0 = (tid >> 4) * 4;
    const int c0 = (tid & 15) * 4;
    float acc[4][4];
    #pragma unroll
    for (int i = 0; i < 4; i++)
        #pragma unroll
        for (int j = 0; j < 4; j++) acc[i][j] = 0.f;

    for (int kt = 0; kt < 16; kt++) {
        __syncthreads();
        {
            const size_t kbase = (size_t)(b*SLEN + kt*64 + r) * D3 + DDIM + h*HD;
            const size_t vbase = kbase + DDIM;
            #pragma unroll
            for (int it = 0; it < 4; it++) {
                int d0 = (seg*4 + it) * 4;
                float4 kv = *(const float4*)(qkv + kbase + d0);
                Ks[(d0+0)*68 + r] = kv.x;
                Ks[(d0+1)*68 + r] = kv.y;
                Ks[(d0+2)*68 + r] = kv.z;
                Ks[(d0+3)*68 + r] = kv.w;
                float4 vv = *(const float4*)(qkv + vbase + d0);
                *(float4*)&Vs[r*68 + d0] = vv;
            }
        }
        __syncthreads();

        float s[4][4];
        #pragma unroll
        for (int i = 0; i < 4; i++)
            #pragma unroll
            for (int j = 0; j < 4; j++) s[i][j] = 0.f;
        #pragma unroll 8
        for (int d = 0; d < 64; d++) {
            float a0 = Qs[d*68 + q0+0], a1 = Qs[d*68 + q0+1];
            float a2 = Qs[d*68 + q0+2], a3 = Qs[d*68 + q0+3];
            float e0 = Ks[d*68 + c0+0], e1 = Ks[d*68 + c0+1];
            float e2 = Ks[d*68 + c0+2], e3 = Ks[d*68 + c0+3];
            s[0][0]=fmaf(a0,e0,s[0][0]); s[0][1]=fmaf(a0,e1,s[0][1]);
            s[0][2]=fmaf(a0,e2,s[0][2]); s[0][3]=fmaf(a0,e3,s[0][3]);
            s[1][0]=fmaf(a1,e0,s[1][0]); s[1][1]=fmaf(a1,e1,s[1][1]);
            s[1][2]=fmaf(a1,e2,s[1][2]); s[1][3]=fmaf(a1,e3,s[1][3]);
            s[2][0]=fmaf(a2,e0,s[2][0]); s[2][1]=fmaf(a2,e1,s[2][1]);
            s[2][2]=fmaf(a2,e2,s[2][2]); s[2][3]=fmaf(a2,e3,s[2][3]);
            s[3][0]=fmaf(a3,e0,s[3][0]); s[3][1]=fmaf(a3,e1,s[3][1]);
            s[3][2]=fmaf(a3,e2,s[3][2]); s[3][3]=fmaf(a3,e3,s[3][3]);
        }
        #pragma unroll
        for (int i = 0; i < 4; i++)
            #pragma unroll
            for (int j = 0; j < 4; j++)
                Pm[(q0+i)*68 + c0+j] = s[i][j] * 0.125f;
        __syncthreads();

        if (tid < 64) {
            float* row = &Pm[tid*68];
            float mold = mrow[tid];
            float mx = mold;
            #pragma unroll 8
            for (int k = 0; k < 64; k++) mx = fmaxf(mx, row[k]);
            float sum = 0.f;
            #pragma unroll 8
            for (int k = 0; k < 64; k++) {
                float e = __expf(row[k] - mx);
                row[k] = e;
                sum += e;
            }
            float sc = __expf(mold - mx);
            lrow[tid] = lrow[tid] * sc + sum;
            mrow[tid] = mx;
            srow[tid] = sc;
        }
        __syncthreads();

        #pragma unroll
        for (int i = 0; i < 4; i++) {
            float sc = srow[q0+i];
            #pragma unroll
            for (int j = 0; j < 4; j++) acc[i][j] *= sc;
        }
        #pragma unroll 8
        for (int k = 0; k < 64; k++) {
            float p0 = Pm[(q0+0)*68 + k], p1 = Pm[(q0+1)*68 + k];
            float p2 = Pm[(q0+2)*68 + k], p3 = Pm[(q0+3)*68 + k];
            float v0 = Vs[k*68 + c0+0], v1 = Vs[k*68 + c0+1];
            float v2 = Vs[k*68 + c0+2], v3 = Vs[k*68 + c0+3];
            acc[0][0]=fmaf(p0,v0,acc[0][0]); acc[0][1]=fmaf(p0,v1,acc[0][1]);
            acc[0][2]=fmaf(p0,v2,acc[0][2]); acc[0][3]=fmaf(p0,v3,acc[0][3]);
            acc[1][0]=fmaf(p1,v0,acc[1][0]); acc[1][1]=fmaf(p1,v1,acc[1][1]);
            acc[1][2]=fmaf(p1,v2,acc[1][2]); acc[1][3]=fmaf(p1,v3,acc[1][3]);
            acc[2][0]=fmaf(p2,v0,acc[2][0]); acc[2][1]=fmaf(p2,v1,acc[2][1]);
            acc[2][2]=fmaf(p2,v2,acc[2][2]); acc[2][3]=fmaf(p2,v3,acc[2][3]);
            acc[3][0]=fmaf(p3,v0,acc[3][0]); acc[3][1]=fmaf(p3,v1,acc[3][1]);
            acc[3][2]=fmaf(p3,v2,acc[3][2]); acc[3][3]=fmaf(p3,v3,acc[3][3]);
        }
    }

    #pragma unroll
    for (int i = 0; i < 4; i++) {
        float linv = 1.f / lrow[q0+i];
        const size_t o = (size_t)(b*SLEN + qt*64 + q0+i) * DDIM + h*HD + c0;
        *(float4*)(out + o) = make_float4(acc[i][0]*linv, acc[i][1]*linv,
                                          acc[i][2]*linv, acc[i][3]*linv);
    }
}

// ---------------------------------------------------------------------------
// Banded attention (|i-j| <= 2). One warp per (b,h,i) query.
// ---------------------------------------------------------------------------
__global__ __launch_bounds__(256)
void attn_band_kernel(const float* __restrict__ qkv, float* __restrict__ out)
{
    const int gw   = (blockIdx.x * blockDim.x + threadIdx.x) >> 5;
    const int lane = threadIdx.x & 31;
    const int i = gw & (SLEN-1);
    const int h = (gw >> 10) & (HNUM-1);
    const int b = gw >> 14;

    const size_t qbase = (size_t)(b*SLEN + i) * D3 + h*HD;
    const float q0 = qkv[qbase + lane];
    const float q1 = qkv[qbase + 32 + lane];

    float sc[5];
    int   jc[5];
    #pragma unroll
    for (int jj = 0; jj < 5; jj++) {
        int j = i - 2 + jj;
        bool valid = (j >= 0) && (j < SLEN);
        jc[jj] = valid ? j : i;
        const size_t kb = (size_t)(b*SLEN + jc[jj]) * D3 + DDIM + h*HD;
        float p = q0 * qkv[kb + lane] + q1 * qkv[kb + 32 + lane];
        #pragma unroll
        for (int off = 16; off; off >>= 1) p += __shfl_xor_sync(0xffffffffu, p, off);
        sc[jj] = valid ? p * 0.125f : -1e30f;
    }
    float mx = sc[0];
    #pragma unroll
    for (int jj = 1; jj < 5; jj++) mx = fmaxf(mx, sc[jj]);
    float w[5], sum = 0.f;
    #pragma unroll
    for (int jj = 0; jj < 5; jj++) { w[jj] = __expf(sc[jj] - mx); sum += w[jj]; }
    const float inv = 1.f / sum;

    float o0 = 0.f, o1 = 0.f;
    #pragma unroll
    for (int jj = 0; jj < 5; jj++) {
        const size_t vb = (size_t)(b*SLEN + jc[jj]) * D3 + 2*DDIM + h*HD;
        o0 = fmaf(w[jj], qkv[vb + lane], o0);
        o1 = fmaf(w[jj], qkv[vb + 32 + lane], o1);
    }
    const size_t ob = (size_t)(b*SLEN + i) * DDIM + h*HD;
    out[ob + lane]      = o0 * inv;
    out[ob + 32 + lane] = o1 * inv;
}

// ---------------------------------------------------------------------------
// LayerNorm: out = LN(a + r) * g + b, optional bf16 hi/lo split outputs.
// ---------------------------------------------------------------------------
__global__ __launch_bounds__(256)
void ln_kernel(const float* __restrict__ a, const float* __restrict__ r,
               const float* __restrict__ g, const float* __restrict__ bt,
               float* __restrict__ out,
               __nv_bfloat16* __restrict__ oh, __nv_bfloat16* __restrict__ ol)
{
    __shared__ float red[2][8];
    __shared__ float s_mean, s_rstd;
    const int n = blockIdx.x;
    const int tid = threadIdx.x;
    const size_t base = (size_t)n * DDIM + tid * 4;

    float4 va = *(const float4*)(a + base);
    if (r) {
        float4 vr = *(const float4*)(r + base);
        va.x += vr.x; va.y += vr.y; va.z += vr.z; va.w += vr.w;
    }
    float s  = va.x + va.y + va.z + va.w;
    float sq = va.x*va.x + va.y*va.y + va.z*va.z + va.w*va.w;

    #pragma unroll
    for (int off = 16; off; off >>= 1) {
        s  += __shfl_xor_sync(0xffffffffu, s,  off);
        sq += __shfl_xor_sync(0xffffffffu, sq, off);
    }
    const int wid = tid >> 5;
    if ((tid & 31) == 0) { red[0][wid] = s; red[1][wid] = sq; }
    __syncthreads();
    if (tid < 32) {
        float ts  = (tid < 8) ? red[0][tid] : 0.f;
        float tsq = (tid < 8) ? red[1][tid] : 0.f;
        #pragma unroll
        for (int off = 4; off; off >>= 1) {
            ts  += __shfl_xor_sync(0xffffffffu, ts,  off);
            tsq += __shfl_xor_sync(0xffffffffu, tsq, off);
        }
        if (tid == 0) {
            float mean = ts * (1.f / DDIM);
            float var  = tsq * (1.f / DDIM) - mean * mean;
            s_mean = mean;
            s_rstd = rsqrtf(var + EPS);
        }
    }
    __syncthreads();
    const float mean = s_mean, rstd = s_rstd;
    float4 gg = *(const float4*)(g + tid*4);
    float4 bb = *(const float4*)(bt + tid*4);
    float4 o;
    o.x = (va.x - mean) * rstd * gg.x + bb.x;
    o.y = (va.y - mean) * rstd * gg.y + bb.y;
    o.z = (va.z - mean) * rstd * gg.z + bb.z;
    o.w = (va.w - mean) * rstd * gg.w + bb.w;
    *(float4*)(out + base) = o;
    if (oh) {
        __nv_bfloat16 h0,h1,h2,h3,l0,l1,l2,l3;
        split1(o.x,h0,l0); split1(o.y,h1,l1); split1(o.z,h2,l2); split1(o.w,h3,l3);
        uint2 uh; uh.x = pack2(h0,h1); uh.y = pack2(h2,h3);
        uint2 ul; ul.x = pack2(l0,l1); ul.y = pack2(l2,l3);
        *(uint2*)(oh + base) = uh;
        *(uint2*)(ol + base) = ul;
    }
}

// ---------------------------------------------------------------------------
// Orchestration
// ---------------------------------------------------------------------------
extern "C" void kernel_launch(void* const* d_in, const int* in_sizes, int n_in,
                              void* d_out, int out_size)
{
    const float* x_in   = (const float*)d_in[0];
    const float* w_in1  = (const float*)d_in[1];
    const float* b_in1  = (const float*)d_in[2];
    const float* w_out1 = (const float*)d_in[3];
    const float* b_out1 = (const float*)d_in[4];
    const float* ln1_g  = (const float*)d_in[5];
    const float* ln1_b  = (const float*)d_in[6];
    const float* w_in2  = (const float*)d_in[7];
    const float* b_in2  = (const float*)d_in[8];
    const float* w_out2 = (const float*)d_in[9];
    const float* b_out2 = (const float*)d_in[10];
    const float* ln2_g  = (const float*)d_in[11];
    const float* ln2_b  = (const float*)d_in[12];
    const float* ffn_w1 = (const float*)d_in[13];
    const float* ffn_b1 = (const float*)d_in[14];
    const float* ffn_w2 = (const float*)d_in[15];
    const float* ffn_b2 = (const float*)d_in[16];
    const float* lnf_g  = (const float*)d_in[17];
    const float* lnf_b  = (const float*)d_in[18];

    float *QKV, *AOUT, *PROJ, *X, *X2, *ATT;
    __nv_bfloat16 *WH, *WL, *P1H, *P1L, *P2H, *P2L;
    cudaGetSymbolAddress((void**)&QKV,  g_qkv);
    cudaGetSymbolAddress((void**)&AOUT, g_aout);
    cudaGetSymbolAddress((void**)&PROJ, g_proj);
    cudaGetSymbolAddress((void**)&X,    g_x);
    cudaGetSymbolAddress((void**)&X2,   g_x2);
    cudaGetSymbolAddress((void**)&ATT,  g_att);
    cudaGetSymbolAddress((void**)&WH,   g_wh);
    cudaGetSymbolAddress((void**)&WL,   g_wl);
    cudaGetSymbolAddress((void**)&P1H,  g_p1h);
    cudaGetSymbolAddress((void**)&P1L,  g_p1l);
    cudaGetSymbolAddress((void**)&P2H,  g_p2h);
    cudaGetSymbolAddress((void**)&P2L,  g_p2l);

    cudaFuncSetAttribute(attn_full_kernel,
                         cudaFuncAttributeMaxDynamicSharedMemorySize, ATTN_SMEM_BYTES);
    cudaFuncSetAttribute(gemm_bf3<0,false,true>,
                         cudaFuncAttributeMaxDynamicSharedMemorySize, GSMEM_BYTES);
    cudaFuncSetAttribute(gemm_bf3<1,true,false>,
                         cudaFuncAttributeMaxDynamicSharedMemorySize, GSMEM_BYTES);
    cudaFuncSetAttribute(gemm_bf3<2,true,true>,
                         cudaFuncAttributeMaxDynamicSharedMemorySize, GSMEM_BYTES);

    const dim3 blk(256);
    const dim3 g_qkvp(D3/128,  NTOK/128);   // (24,16)
    const dim3 g_outp(DDIM/128, NTOK/128);  // (8,16)
    const dim3 g_ffn1(MDIM/128, NTOK/128);  // (32,16)
    const dim3 g_attn(BNUM*HNUM, SLEN/64);
    const int  g_band = (BNUM*HNUM*SLEN*32) / 256;
    const int  g_ln   = NTOK;

    // ---- weight splits (run every launch; graph-captured) ----
    split_kernel<<<(W_OUT1_OFF-W_IN1_OFF)/1024, blk>>>(w_in1,  WH+W_IN1_OFF,  WL+W_IN1_OFF);
    split_kernel<<<(W_IN2_OFF-W_OUT1_OFF)/1024, blk>>>(w_out1, WH+W_OUT1_OFF, WL+W_OUT1_OFF);
    split_kernel<<<(W_OUT2_OFF-W_IN2_OFF)/1024, blk>>>(w_in2,  WH+W_IN2_OFF,  WL+W_IN2_OFF);
    split_kernel<<<(FW1_OFF-W_OUT2_OFF)/1024, blk>>>(w_out2, WH+W_OUT2_OFF, WL+W_OUT2_OFF);
    split_kernel<<<(FW2_OFF-FW1_OFF)/1024, blk>>>(ffn_w1, WH+FW1_OFF,    WL+FW1_OFF);
    split_kernel<<<(WTOTAL-FW2_OFF)/1024, blk>>>(ffn_w2, WH+FW2_OFF,    WL+FW2_OFF);

    // initial activation split (layer-0 input)
    split_kernel<<<(NTOK*DDIM)/1024, blk>>>(x_in, P1H, P1L);

    const float* xcur = x_in;
    for (int l = 0; l < LNUM; l++) {
        const size_t oW3 = (size_t)l * D3 * DDIM;
        const size_t oW1 = (size_t)l * DDIM * DDIM;
        const size_t oWm = (size_t)l * MDIM * DDIM;

        // ---- intra-frame full MHA ----
        gemm_bf3<0,false,true><<<g_qkvp, blk, GSMEM_BYTES>>>(
            P1H, P1L, WH+W_IN1_OFF+oW3, WL+W_IN1_OFF+oW3,
            b_in1 + (size_t)l*D3, nullptr, QKV, nullptr, nullptr, NTOK, D3, DDIM);
        attn_full_kernel<<<g_attn, blk, ATTN_SMEM_BYTES>>>(QKV, AOUT);
        split_kernel<<<(NTOK*DDIM)/1024, blk>>>(AOUT, P1H, P1L);
        gemm_bf3<0,false,true><<<g_outp, blk, GSMEM_BYTES>>>(
            P1H, P1L, WH+W_OUT1_OFF+oW1, WL+W_OUT1_OFF+oW1,
            b_out1 + (size_t)l*DDIM, nullptr, PROJ, nullptr, nullptr, NTOK, DDIM, DDIM);
        ln_kernel<<<g_ln, blk>>>(PROJ, xcur, ln1_g + (size_t)l*DDIM,
                                 ln1_b + (size_t)l*DDIM, X2, P1H, P1L);

        // ---- inter-frame banded MHA ----
        gemm_bf3<0,false,true><<<g_qkvp, blk, GSMEM_BYTES>>>(
            P1H, P1L, WH+W_IN2_OFF+oW3, WL+W_IN2_OFF+oW3,
            b_in2 + (size_t)l*D3, nullptr, QKV, nullptr, nullptr, NTOK, D3, DDIM);
        attn_band_kernel<<<g_band, blk>>>(QKV, AOUT);
        split_kernel<<<(NTOK*DDIM)/1024, blk>>>(AOUT, P1H, P1L);
        gemm_bf3<0,false,true><<<g_outp, blk, GSMEM_BYTES>>>(
            P1H, P1L, WH+W_OUT2_OFF+oW1, WL+W_OUT2_OFF+oW1,
            b_out2 + (size_t)l*DDIM, nullptr, PROJ, nullptr, nullptr, NTOK, DDIM, DDIM);
        ln_kernel<<<g_ln, blk>>>(PROJ, X2, ln2_g + (size_t)l*DDIM,
                                 ln2_b + (size_t)l*DDIM, ATT, P1H, P1L);

        // ---- FFN ----
        gemm_bf3<1,true,false><<<g_ffn1, blk, GSMEM_BYTES>>>(
            P1H, P1L, WH+FW1_OFF+oWm, WL+FW1_OFF+oWm,
            ffn_b1 + (size_t)l*MDIM, nullptr, nullptr, P2H, P2L, NTOK, MDIM, DDIM);
        gemm_bf3<2,true,true><<<g_outp, blk, GSMEM_BYTES>>>(
            P2H, P2L, WH+FW2_OFF+oWm, WL+FW2_OFF+oWm,
            ffn_b2 + (size_t)l*DDIM, ATT, X, P1H, P1L, NTOK, DDIM, MDIM);
        xcur = X;
    }

    ln_kernel<<<g_ln, blk>>>(xcur, nullptr, lnf_g, lnf_b, (float*)d_out,
                             nullptr, nullptr);
}

// round 4
// speedup vs baseline: 2.0803x; 1.1413x over previous
#include <cuda_runtime.h>
#include <cuda_bf16.h>
#include <math.h>
#include <stdint.h>

// ---------------------------------------------------------------------------
// Problem constants
// ---------------------------------------------------------------------------
#define LNUM 4
#define DDIM 1024
#define HNUM 16
#define HD   64
#define MDIM 4096
#define SLEN 1024
#define BNUM 2
#define NTOK (BNUM*SLEN)        // 2048
#define D3   (3*DDIM)           // 3072
#define EPS  1e-5f

// Weight split array layout (element offsets)
#define W_IN1_OFF   0u
#define W_OUT1_OFF  12582912u
#define W_IN2_OFF   16777216u
#define W_OUT2_OFF  29360128u
#define FW1_OFF     33554432u
#define FW2_OFF     50331648u
#define WTOTAL      67108864u

// ---------------------------------------------------------------------------
// Device scratch (no allocations allowed)
// ---------------------------------------------------------------------------
static __device__ float g_proj[NTOK*DDIM];
static __device__ float g_x   [NTOK*DDIM];
static __device__ float g_x2  [NTOK*DDIM];
static __device__ float g_att [NTOK*DDIM];

static __device__ __nv_bfloat16 g_wh[WTOTAL];        // weight hi
static __device__ __nv_bfloat16 g_wl[WTOTAL];        // weight lo
static __device__ __nv_bfloat16 g_qkvh[NTOK*D3];     // qkv hi
static __device__ __nv_bfloat16 g_qkvl[NTOK*D3];     // qkv lo
static __device__ __nv_bfloat16 g_p1h[NTOK*DDIM];    // activation split (1024 wide)
static __device__ __nv_bfloat16 g_p1l[NTOK*DDIM];
static __device__ __nv_bfloat16 g_p2h[NTOK*MDIM];    // activation split (4096 wide)
static __device__ __nv_bfloat16 g_p2l[NTOK*MDIM];

// ---------------------------------------------------------------------------
// Helpers
// ---------------------------------------------------------------------------
__device__ __forceinline__ void cp16(uint32_t d, const void* s) {
    asm volatile("cp.async.cg.shared.global [%0], [%1], 16;\n" :: "r"(d), "l"(s));
}
__device__ __forceinline__ void cp_commit() {
    asm volatile("cp.async.commit_group;\n" ::: "memory");
}
__device__ __forceinline__ void cp_wait1() {
    asm volatile("cp.async.wait_group 1;\n" ::: "memory");
}
__device__ __forceinline__ void cp_wait0() {
    asm volatile("cp.async.wait_group 0;\n" ::: "memory");
}
__device__ __forceinline__ void ldsm4(uint32_t* r, uint32_t a) {
    asm volatile("ldmatrix.sync.aligned.m8n8.x4.shared.b16 {%0,%1,%2,%3}, [%4];"
        : "=r"(r[0]), "=r"(r[1]), "=r"(r[2]), "=r"(r[3]) : "r"(a));
}
__device__ __forceinline__ void ldsm4t(uint32_t* r, uint32_t a) {
    asm volatile("ldmatrix.sync.aligned.m8n8.x4.trans.shared.b16 {%0,%1,%2,%3}, [%4];"
        : "=r"(r[0]), "=r"(r[1]), "=r"(r[2]), "=r"(r[3]) : "r"(a));
}
__device__ __forceinline__ void mma16816(float* c, const uint32_t* a,
                                         uint32_t b0, uint32_t b1) {
    asm volatile(
        "mma.sync.aligned.m16n8k16.row.col.f32.bf16.bf16.f32 "
        "{%0,%1,%2,%3},{%4,%5,%6,%7},{%8,%9},{%0,%1,%2,%3};"
        : "+f"(c[0]), "+f"(c[1]), "+f"(c[2]), "+f"(c[3])
        : "r"(a[0]), "r"(a[1]), "r"(a[2]), "r"(a[3]), "r"(b0), "r"(b1));
}
__device__ __forceinline__ uint32_t pack2(__nv_bfloat16 a, __nv_bfloat16 b) {
    __nv_bfloat162 t = __halves2bfloat162(a, b);
    return *reinterpret_cast<uint32_t*>(&t);
}
__device__ __forceinline__ void split1(float v, __nv_bfloat16& h, __nv_bfloat16& l) {
    h = __float2bfloat16(v);
    l = __float2bfloat16(v - __bfloat162float(h));
}
__device__ __forceinline__ float bf2f(__nv_bfloat16 v) { return __bfloat162float(v); }

// ---------------------------------------------------------------------------
// fp32 -> (hi,lo) bf16 split kernel. n must be a multiple of 1024.
// ---------------------------------------------------------------------------
__global__ __launch_bounds__(256)
void split_kernel(const float* __restrict__ in, __nv_bfloat16* __restrict__ hi,
                  __nv_bfloat16* __restrict__ lo)
{
    const size_t i = ((size_t)blockIdx.x * 256 + threadIdx.x) * 4;
    float4 v = *(const float4*)(in + i);
    __nv_bfloat16 h0,h1,h2,h3,l0,l1,l2,l3;
    split1(v.x,h0,l0); split1(v.y,h1,l1); split1(v.z,h2,l2); split1(v.w,h3,l3);
    uint2 uh; uh.x = pack2(h0,h1); uh.y = pack2(h2,h3);
    uint2 ul; ul.x = pack2(l0,l1); ul.y = pack2(l2,l3);
    *(uint2*)(hi + i) = uh;
    *(uint2*)(lo + i) = ul;
}

// ---------------------------------------------------------------------------
// bf16x3 tensor-core GEMM (unchanged from round 3, known good).
// ---------------------------------------------------------------------------
#define STAGE_BYTES 32768
#define GSMEM_BYTES (2*STAGE_BYTES)

template<int EPI, bool OSPLIT, bool OF32>
__global__ __launch_bounds__(256)
void gemm_bf3(const __nv_bfloat16* __restrict__ Ah, const __nv_bfloat16* __restrict__ Al,
              const __nv_bfloat16* __restrict__ Bh, const __nv_bfloat16* __restrict__ Bl,
              const float* __restrict__ bias, const float* __restrict__ Res,
              float* __restrict__ C, __nv_bfloat16* __restrict__ Chi,
              __nv_bfloat16* __restrict__ Clo, int M, int N, int K)
{
    extern __shared__ __nv_bfloat16 smbuf[];
    const uint32_t smem_u32 = (uint32_t)__cvta_generic_to_shared(smbuf);

    const int tid = threadIdx.x;
    const int m0 = blockIdx.y * 128;
    const int n0 = blockIdx.x * 128;

    const int m_ld  = tid & 127;
    const int ko_ld = tid >> 7;
    const uint32_t oC1 = (uint32_t)(((ko_ld    )*128 + m_ld) * 8) * 2;
    const uint32_t oC2 = (uint32_t)(((ko_ld + 2)*128 + m_ld) * 8) * 2;

    const __nv_bfloat16* pAh = Ah + (size_t)(m0 + m_ld) * K + ko_ld * 8;
    const __nv_bfloat16* pAl = Al + (size_t)(m0 + m_ld) * K + ko_ld * 8;
    const __nv_bfloat16* pBh = Bh + (size_t)(n0 + m_ld) * K + ko_ld * 8;
    const __nv_bfloat16* pBl = Bl + (size_t)(n0 + m_ld) * K + ko_ld * 8;

    const int wid  = tid >> 5;
    const int lane = tid & 31;
    const int wm = (wid >> 2) * 64;
    const int wn = (wid & 3) * 32;
    const int a_row = lane & 15;
    const int a_ko  = lane >> 4;
    const int b_row = (lane & 7) + ((lane & 16) >> 1);
    const int b_ko  = (lane >> 3) & 1;

    const uint32_t aoff = (uint32_t)((a_ko*1024 + (wm + a_row)*8) * 2);
    const uint32_t boff = (uint32_t)((b_ko*1024 + (wn + b_row)*8) * 2);

    float acc[4][4][4];
    #pragma unroll
    for (int i = 0; i < 4; i++)
        #pragma unroll
        for (int j = 0; j < 4; j++)
            #pragma unroll
            for (int e = 0; e < 4; e++) acc[i][j][e] = 0.f;

    const int T = K >> 5;

    auto load_stage = [&](int kt, int s) {
        const uint32_t sb = smem_u32 + s * STAGE_BYTES;
        const size_t gk = (size_t)kt * 32;
        cp16(sb + oC1,          pAh + gk);
        cp16(sb + oC2,          pAh + gk + 16);
        cp16(sb + 8192  + oC1,  pAl + gk);
        cp16(sb + 8192  + oC2,  pAl + gk + 16);
        cp16(sb + 16384 + oC1,  pBh + gk);
        cp16(sb + 16384 + oC2,  pBh + gk + 16);
        cp16(sb + 24576 + oC1,  pBl + gk);
        cp16(sb + 24576 + oC2,  pBl + gk + 16);
        cp_commit();
    };

    load_stage(0, 0);

    for (int kt = 0; kt < T; kt++) {
        const int s = kt & 1;
        if (kt + 1 < T) {
            load_stage(kt + 1, s ^ 1);
            cp_wait1();
        } else {
            cp_wait0();
        }
        __syncthreads();

        const uint32_t sb = smem_u32 + s * STAGE_BYTES;
        #pragma unroll
        for (int ko0 = 0; ko0 < 4; ko0 += 2) {
            uint32_t a_h[4][4], a_l[4][4], b_h[8], b_l[8];
            #pragma unroll
            for (int mf = 0; mf < 4; mf++) {
                const uint32_t ad = sb + aoff + (uint32_t)ko0*2048 + (uint32_t)mf*256;
                ldsm4(a_h[mf], ad);
                ldsm4(a_l[mf], ad + 8192);
            }
            #pragma unroll
            for (int nf2 = 0; nf2 < 2; nf2++) {
                const uint32_t bd = sb + 16384 + boff + (uint32_t)ko0*2048 + (uint32_t)nf2*256;
                ldsm4(&b_h[nf2*4], bd);
                ldsm4(&b_l[nf2*4], bd + 8192);
            }
            #pragma unroll
            for (int mf = 0; mf < 4; mf++)
                #pragma unroll
                for (int nf = 0; nf < 4; nf++) {
                    mma16816(acc[mf][nf], a_h[mf], b_h[nf*2], b_h[nf*2+1]);
                    mma16816(acc[mf][nf], a_h[mf], b_l[nf*2], b_l[nf*2+1]);
                    mma16816(acc[mf][nf], a_l[mf], b_h[nf*2], b_h[nf*2+1]);
                }
        }
        __syncthreads();
    }

    const int er = lane >> 2;
    const int ec = (lane & 3) * 2;
    #pragma unroll
    for (int mf = 0; mf < 4; mf++) {
        #pragma unroll
        for (int nf = 0; nf < 4; nf++) {
            const int m = m0 + wm + mf*16 + er;
            const int n = n0 + wn + nf*8 + ec;
            const float2 bv = *(const float2*)(bias + n);
            #pragma unroll
            for (int half = 0; half < 2; half++) {
                const int mm = m + half*8;
                float t0 = acc[mf][nf][half*2+0] + bv.x;
                float t1 = acc[mf][nf][half*2+1] + bv.y;
                if (EPI == 1) {
                    t0 = 0.5f * t0 * (1.f + erff(t0 * 0.70710678118654752f));
                    t1 = 0.5f * t1 * (1.f + erff(t1 * 0.70710678118654752f));
                }
                if (EPI == 2) {
                    const float2 rv = *(const float2*)(Res + (size_t)mm * N + n);
                    t0 += rv.x; t1 += rv.y;
                }
                if (OF32) {
                    *(float2*)(C + (size_t)mm * N + n) = make_float2(t0, t1);
                }
                if (OSPLIT) {
                    __nv_bfloat16 h0,h1,l0,l1;
                    split1(t0,h0,l0); split1(t1,h1,l1);
                    *(uint32_t*)(Chi + (size_t)mm * N + n) = pack2(h0,h1);
                    *(uint32_t*)(Clo + (size_t)mm * N + n) = pack2(l0,l1);
                }
            }
        }
    }
}

// ---------------------------------------------------------------------------
// Tensor-core full attention (bf16x3 flash). 4 warps per block; block handles
// (b,h) x 64-query tile; iterates 16 key tiles of 64 with cp.async double
// buffering. qkv input as bf16 hi/lo [tok][3D]; output written pre-split into
// oh/ol [tok][D].
// Smem: Q(h,l) 16KB + 2 stages x (K(h,l)+V(h,l)) 32KB = 81920 bytes.
// ---------------------------------------------------------------------------
#define ATTN_TC_SMEM 81920

__global__ __launch_bounds__(128)
void attn_tc_kernel(const __nv_bfloat16* __restrict__ qkvh,
                    const __nv_bfloat16* __restrict__ qkvl,
                    __nv_bfloat16* __restrict__ oh,
                    __nv_bfloat16* __restrict__ ol)
{
    extern __shared__ char smc[];
    const uint32_t sb = (uint32_t)__cvta_generic_to_shared(smc);

    const int bh = blockIdx.x;           // 0..31
    const int b  = bh >> 4;
    const int h  = bh & 15;
    const int qt = blockIdx.y;           // 0..15
    const int tid  = threadIdx.x;
    const int wid  = tid >> 5;
    const int lane = tid & 31;

    // ---- cp.async layouts ----
    const int r    = tid >> 1;           // 0..63 row
    const int koh  = (tid & 1) * 4;      // ko half: 0 or 4

    // Q tile load (hi at sb+0, lo at sb+8192)
    {
        const size_t qrow = (size_t)(b*SLEN + qt*64 + r) * D3 + h*HD;
        #pragma unroll
        for (int it = 0; it < 4; it++) {
            const int ko = koh + it;
            const uint32_t dst = sb + (uint32_t)(((ko*64 + r)*8) * 2);
            cp16(dst,        qkvh + qrow + ko*8);
            cp16(dst + 8192, qkvl + qrow + ko*8);
        }
    }

    auto load_kv = [&](int kt, int s) {
        const uint32_t stg = sb + 16384 + (uint32_t)s * 32768;
        const size_t krow = (size_t)(b*SLEN + kt*64 + r) * D3 + DDIM + h*HD;
        const size_t vrow = krow + DDIM;
        #pragma unroll
        for (int it = 0; it < 4; it++) {
            const int ko = koh + it;
            const uint32_t off = (uint32_t)(((ko*64 + r)*8) * 2);
            cp16(stg + off,          qkvh + krow + ko*8);
            cp16(stg + 8192  + off,  qkvl + krow + ko*8);
            cp16(stg + 16384 + off,  qkvh + vrow + ko*8);
            cp16(stg + 24576 + off,  qkvl + vrow + ko*8);
        }
    };

    load_kv(0, 0);
    cp_commit();          // group: Q + stage0

    // ---- fragment address components ----
    const int a_row = lane & 15;
    const int a_ko  = lane >> 4;
    const int b_row = (lane & 7) + ((lane & 16) >> 1);
    const int b_ko  = (lane >> 3) & 1;
    const int v_key = lane & 15;
    const int v_ko  = lane >> 4;

    uint32_t qa_h[4][4], qa_l[4][4];

    float m0 = -1e30f, m1 = -1e30f, l0 = 0.f, l1 = 0.f;
    float oacc[8][4];
    #pragma unroll
    for (int nf = 0; nf < 8; nf++)
        #pragma unroll
        for (int e = 0; e < 4; e++) oacc[nf][e] = 0.f;

    for (int kt = 0; kt < 16; kt++) {
        const int s = kt & 1;
        if (kt + 1 < 16) {
            load_kv(kt + 1, s ^ 1);
            cp_commit();
            cp_wait1();
        } else {
            cp_wait0();
        }
        __syncthreads();

        if (kt == 0) {
            // preload Q fragments (reused for all key tiles)
            #pragma unroll
            for (int ks = 0; ks < 4; ks++) {
                const uint32_t ad = sb +
                    (uint32_t)((((ks*2 + a_ko)*64 + wid*16 + a_row)*8) * 2);
                ldsm4(qa_h[ks], ad);
                ldsm4(qa_l[ks], ad + 8192);
            }
        }

        const uint32_t stg = sb + 16384 + (uint32_t)s * 32768;

        // ---- S = Q K^T (bf16x3) ----
        float sc[8][4];
        #pragma unroll
        for (int nf = 0; nf < 8; nf++)
            #pragma unroll
            for (int e = 0; e < 4; e++) sc[nf][e] = 0.f;

        #pragma unroll
        for (int ks = 0; ks < 4; ks++) {
            #pragma unroll
            for (int np = 0; np < 4; np++) {
                uint32_t kb[4], kl[4];
                const uint32_t kd = stg +
                    (uint32_t)((((ks*2 + b_ko)*64 + np*16 + b_row)*8) * 2);
                ldsm4(kb, kd);
                ldsm4(kl, kd + 8192);
                mma16816(sc[2*np],   qa_h[ks], kb[0], kb[1]);
                mma16816(sc[2*np],   qa_h[ks], kl[0], kl[1]);
                mma16816(sc[2*np],   qa_l[ks], kb[0], kb[1]);
                mma16816(sc[2*np+1], qa_h[ks], kb[2], kb[3]);
                mma16816(sc[2*np+1], qa_h[ks], kl[2], kl[3]);
                mma16816(sc[2*np+1], qa_l[ks], kb[2], kb[3]);
            }
        }

        // ---- online softmax (rows er=lane>>2 and er+8) ----
        #pragma unroll
        for (int nf = 0; nf < 8; nf++)
            #pragma unroll
            for (int e = 0; e < 4; e++) sc[nf][e] *= 0.125f;

        float mx0 = m0, mx1 = m1;
        #pragma unroll
        for (int nf = 0; nf < 8; nf++) {
            mx0 = fmaxf(mx0, fmaxf(sc[nf][0], sc[nf][1]));
            mx1 = fmaxf(mx1, fmaxf(sc[nf][2], sc[nf][3]));
        }
        mx0 = fmaxf(mx0, __shfl_xor_sync(0xffffffffu, mx0, 1));
        mx0 = fmaxf(mx0, __shfl_xor_sync(0xffffffffu, mx0, 2));
        mx1 = fmaxf(mx1, __shfl_xor_sync(0xffffffffu, mx1, 1));
        mx1 = fmaxf(mx1, __shfl_xor_sync(0xffffffffu, mx1, 2));

        const float al0 = __expf(m0 - mx0);
        const float al1 = __expf(m1 - mx1);
        m0 = mx0; m1 = mx1;

        float s0 = 0.f, s1 = 0.f;
        uint32_t pah[4][4], pal[4][4];
        #pragma unroll
        for (int nf = 0; nf < 8; nf++) {
            const float p0 = __expf(sc[nf][0] - m0);
            const float p1 = __expf(sc[nf][1] - m0);
            const float p2 = __expf(sc[nf][2] - m1);
            const float p3 = __expf(sc[nf][3] - m1);
            s0 += p0 + p1;
            s1 += p2 + p3;
            __nv_bfloat16 h0,h1,h2,h3,lo0,lo1,lo2,lo3;
            split1(p0,h0,lo0); split1(p1,h1,lo1);
            split1(p2,h2,lo2); split1(p3,h3,lo3);
            const int ks = nf >> 1;
            const int hv = (nf & 1) * 2;
            pah[ks][hv+0] = pack2(h0, h1);
            pah[ks][hv+1] = pack2(h2, h3);
            pal[ks][hv+0] = pack2(lo0, lo1);
            pal[ks][hv+1] = pack2(lo2, lo3);
        }
        s0 += __shfl_xor_sync(0xffffffffu, s0, 1);
        s0 += __shfl_xor_sync(0xffffffffu, s0, 2);
        s1 += __shfl_xor_sync(0xffffffffu, s1, 1);
        s1 += __shfl_xor_sync(0xffffffffu, s1, 2);
        l0 = l0 * al0 + s0;
        l1 = l1 * al1 + s1;

        #pragma unroll
        for (int nf = 0; nf < 8; nf++) {
            oacc[nf][0] *= al0; oacc[nf][1] *= al0;
            oacc[nf][2] *= al1; oacc[nf][3] *= al1;
        }

        // ---- O += P V (bf16x3) ----
        #pragma unroll
        for (int ks = 0; ks < 4; ks++) {
            #pragma unroll
            for (int np = 0; np < 4; np++) {
                uint32_t vb[4], vl[4];
                const uint32_t vd = stg + 16384 +
                    (uint32_t)((((np*2 + v_ko)*64 + ks*16 + v_key)*8) * 2);
                ldsm4t(vb, vd);
                ldsm4t(vl, vd + 8192);
                mma16816(oacc[2*np],   pah[ks], vb[0], vb[1]);
                mma16816(oacc[2*np],   pah[ks], vl[0], vl[1]);
                mma16816(oacc[2*np],   pal[ks], vb[0], vb[1]);
                mma16816(oacc[2*np+1], pah[ks], vb[2], vb[3]);
                mma16816(oacc[2*np+1], pah[ks], vl[2], vl[3]);
                mma16816(oacc[2*np+1], pal[ks], vb[2], vb[3]);
            }
        }
        __syncthreads();   // all warps done with stage s before it is refilled
    }

    // ---- epilogue: divide by l, split, store ----
    const float inv0 = 1.f / l0;
    const float inv1 = 1.f / l1;
    const int er  = lane >> 2;
    const int ec  = (lane & 3) * 2;
    const int tok0 = b*SLEN + qt*64 + wid*16 + er;
    const int tok1 = tok0 + 8;
    #pragma unroll
    for (int nf = 0; nf < 8; nf++) {
        const int col = h*HD + nf*8 + ec;
        const float o0 = oacc[nf][0] * inv0;
        const float o1 = oacc[nf][1] * inv0;
        const float o2 = oacc[nf][2] * inv1;
        const float o3 = oacc[nf][3] * inv1;
        __nv_bfloat16 h0,h1,h2,h3,lo0,lo1,lo2,lo3;
        split1(o0,h0,lo0); split1(o1,h1,lo1);
        split1(o2,h2,lo2); split1(o3,h3,lo3);
        *(uint32_t*)(oh + (size_t)tok0 * DDIM + col) = pack2(h0, h1);
        *(uint32_t*)(ol + (size_t)tok0 * DDIM + col) = pack2(lo0, lo1);
        *(uint32_t*)(oh + (size_t)tok1 * DDIM + col) = pack2(h2, h3);
        *(uint32_t*)(ol + (size_t)tok1 * DDIM + col) = pack2(lo2, lo3);
    }
}

// ---------------------------------------------------------------------------
// Banded attention (|i-j| <= 2). One warp per (b,h,i) query. Reads hi+lo.
// Output written pre-split into oh/ol.
// ---------------------------------------------------------------------------
__global__ __launch_bounds__(256)
void attn_band_kernel(const __nv_bfloat16* __restrict__ qkvh,
                      const __nv_bfloat16* __restrict__ qkvl,
                      __nv_bfloat16* __restrict__ oh,
                      __nv_bfloat16* __restrict__ ol)
{
    const int gw   = (blockIdx.x * blockDim.x + threadIdx.x) >> 5;
    const int lane = threadIdx.x & 31;
    const int i = gw & (SLEN-1);
    const int h = (gw >> 10) & (HNUM-1);
    const int b = gw >> 14;

    const size_t qbase = (size_t)(b*SLEN + i) * D3 + h*HD;
    const float q0 = bf2f(qkvh[qbase + lane])      + bf2f(qkvl[qbase + lane]);
    const float q1 = bf2f(qkvh[qbase + 32 + lane]) + bf2f(qkvl[qbase + 32 + lane]);

    float sc[5];
    int   jc[5];
    #pragma unroll
    for (int jj = 0; jj < 5; jj++) {
        int j = i - 2 + jj;
        bool valid = (j >= 0) && (j < SLEN);
        jc[jj] = valid ? j : i;
        const size_t kb = (size_t)(b*SLEN + jc[jj]) * D3 + DDIM + h*HD;
        const float k0 = bf2f(qkvh[kb + lane])      + bf2f(qkvl[kb + lane]);
        const float k1 = bf2f(qkvh[kb + 32 + lane]) + bf2f(qkvl[kb + 32 + lane]);
        float p = q0 * k0 + q1 * k1;
        #pragma unroll
        for (int off = 16; off; off >>= 1) p += __shfl_xor_sync(0xffffffffu, p, off);
        sc[jj] = valid ? p * 0.125f : -1e30f;
    }
    float mx = sc[0];
    #pragma unroll
    for (int jj = 1; jj < 5; jj++) mx = fmaxf(mx, sc[jj]);
    float w[5], sum = 0.f;
    #pragma unroll
    for (int jj = 0; jj < 5; jj++) { w[jj] = __expf(sc[jj] - mx); sum += w[jj]; }
    const float inv = 1.f / sum;

    float o0 = 0.f, o1 = 0.f;
    #pragma unroll
    for (int jj = 0; jj < 5; jj++) {
        const size_t vb = (size_t)(b*SLEN + jc[jj]) * D3 + 2*DDIM + h*HD;
        const float v0 = bf2f(qkvh[vb + lane])      + bf2f(qkvl[vb + lane]);
        const float v1 = bf2f(qkvh[vb + 32 + lane]) + bf2f(qkvl[vb + 32 + lane]);
        o0 = fmaf(w[jj], v0, o0);
        o1 = fmaf(w[jj], v1, o1);
    }
    o0 *= inv; o1 *= inv;

    const size_t ob = (size_t)(b*SLEN + i) * DDIM + h*HD;
    __nv_bfloat16 hh, ll;
    split1(o0, hh, ll);
    oh[ob + lane] = hh;  ol[ob + lane] = ll;
    split1(o1, hh, ll);
    oh[ob + 32 + lane] = hh;  ol[ob + 32 + lane] = ll;
}

// ---------------------------------------------------------------------------
// LayerNorm: out = LN(a + r) * g + b, optional bf16 hi/lo split outputs.
// ---------------------------------------------------------------------------
__global__ __launch_bounds__(256)
void ln_kernel(const float* __restrict__ a, const float* __restrict__ r,
               const float* __restrict__ g, const float* __restrict__ bt,
               float* __restrict__ out,
               __nv_bfloat16* __restrict__ ohh, __nv_bfloat16* __restrict__ oll)
{
    __shared__ float red[2][8];
    __shared__ float s_mean, s_rstd;
    const int n = blockIdx.x;
    const int tid = threadIdx.x;
    const size_t base = (size_t)n * DDIM + tid * 4;

    float4 va = *(const float4*)(a + base);
    if (r) {
        float4 vr = *(const float4*)(r + base);
        va.x += vr.x; va.y += vr.y; va.z += vr.z; va.w += vr.w;
    }
    float s  = va.x + va.y + va.z + va.w;
    float sq = va.x*va.x + va.y*va.y + va.z*va.z + va.w*va.w;

    #pragma unroll
    for (int off = 16; off; off >>= 1) {
        s  += __shfl_xor_sync(0xffffffffu, s,  off);
        sq += __shfl_xor_sync(0xffffffffu, sq, off);
    }
    const int wid = tid >> 5;
    if ((tid & 31) == 0) { red[0][wid] = s; red[1][wid] = sq; }
    __syncthreads();
    if (tid < 32) {
        float ts  = (tid < 8) ? red[0][tid] : 0.f;
        float tsq = (tid < 8) ? red[1][tid] : 0.f;
        #pragma unroll
        for (int off = 4; off; off >>= 1) {
            ts  += __shfl_xor_sync(0xffffffffu, ts,  off);
            tsq += __shfl_xor_sync(0xffffffffu, tsq, off);
        }
        if (tid == 0) {
            float mean = ts * (1.f / DDIM);
            float var  = tsq * (1.f / DDIM) - mean * mean;
            s_mean = mean;
            s_rstd = rsqrtf(var + EPS);
        }
    }
    __syncthreads();
    const float mean = s_mean, rstd = s_rstd;
    float4 gg = *(const float4*)(g + tid*4);
    float4 bb = *(const float4*)(bt + tid*4);
    float4 o;
    o.x = (va.x - mean) * rstd * gg.x + bb.x;
    o.y = (va.y - mean) * rstd * gg.y + bb.y;
    o.z = (va.z - mean) * rstd * gg.z + bb.z;
    o.w = (va.w - mean) * rstd * gg.w + bb.w;
    *(float4*)(out + base) = o;
    if (ohh) {
        __nv_bfloat16 h0,h1,h2,h3,l0,l1,l2,l3;
        split1(o.x,h0,l0); split1(o.y,h1,l1); split1(o.z,h2,l2); split1(o.w,h3,l3);
        uint2 uh; uh.x = pack2(h0,h1); uh.y = pack2(h2,h3);
        uint2 ul; ul.x = pack2(l0,l1); ul.y = pack2(l2,l3);
        *(uint2*)(ohh + base) = uh;
        *(uint2*)(oll + base) = ul;
    }
}

// ---------------------------------------------------------------------------
// Orchestration
// ---------------------------------------------------------------------------
extern "C" void kernel_launch(void* const* d_in, const int* in_sizes, int n_in,
                              void* d_out, int out_size)
{
    const float* x_in   = (const float*)d_in[0];
    const float* w_in1  = (const float*)d_in[1];
    const float* b_in1  = (const float*)d_in[2];
    const float* w_out1 = (const float*)d_in[3];
    const float* b_out1 = (const float*)d_in[4];
    const float* ln1_g  = (const float*)d_in[5];
    const float* ln1_b  = (const float*)d_in[6];
    const float* w_in2  = (const float*)d_in[7];
    const float* b_in2  = (const float*)d_in[8];
    const float* w_out2 = (const float*)d_in[9];
    const float* b_out2 = (const float*)d_in[10];
    const float* ln2_g  = (const float*)d_in[11];
    const float* ln2_b  = (const float*)d_in[12];
    const float* ffn_w1 = (const float*)d_in[13];
    const float* ffn_b1 = (const float*)d_in[14];
    const float* ffn_w2 = (const float*)d_in[15];
    const float* ffn_b2 = (const float*)d_in[16];
    const float* lnf_g  = (const float*)d_in[17];
    const float* lnf_b  = (const float*)d_in[18];

    float *PROJ, *X, *X2, *ATT;
    __nv_bfloat16 *WH, *WL, *QKVH, *QKVL, *P1H, *P1L, *P2H, *P2L;
    cudaGetSymbolAddress((void**)&PROJ, g_proj);
    cudaGetSymbolAddress((void**)&X,    g_x);
    cudaGetSymbolAddress((void**)&X2,   g_x2);
    cudaGetSymbolAddress((void**)&ATT,  g_att);
    cudaGetSymbolAddress((void**)&WH,   g_wh);
    cudaGetSymbolAddress((void**)&WL,   g_wl);
    cudaGetSymbolAddress((void**)&QKVH, g_qkvh);
    cudaGetSymbolAddress((void**)&QKVL, g_qkvl);
    cudaGetSymbolAddress((void**)&P1H,  g_p1h);
    cudaGetSymbolAddress((void**)&P1L,  g_p1l);
    cudaGetSymbolAddress((void**)&P2H,  g_p2h);
    cudaGetSymbolAddress((void**)&P2L,  g_p2l);

    cudaFuncSetAttribute(attn_tc_kernel,
                         cudaFuncAttributeMaxDynamicSharedMemorySize, ATTN_TC_SMEM);
    cudaFuncSetAttribute(gemm_bf3<0,false,true>,
                         cudaFuncAttributeMaxDynamicSharedMemorySize, GSMEM_BYTES);
    cudaFuncSetAttribute(gemm_bf3<0,true,false>,
                         cudaFuncAttributeMaxDynamicSharedMemorySize, GSMEM_BYTES);
    cudaFuncSetAttribute(gemm_bf3<1,true,false>,
                         cudaFuncAttributeMaxDynamicSharedMemorySize, GSMEM_BYTES);
    cudaFuncSetAttribute(gemm_bf3<2,true,true>,
                         cudaFuncAttributeMaxDynamicSharedMemorySize, GSMEM_BYTES);

    const dim3 blk(256);
    const dim3 g_qkvp(D3/128,  NTOK/128);   // (24,16)
    const dim3 g_outp(DDIM/128, NTOK/128);  // (8,16)
    const dim3 g_ffn1(MDIM/128, NTOK/128);  // (32,16)
    const dim3 g_attn(BNUM*HNUM, SLEN/64);  // (32,16)
    const int  g_band = (BNUM*HNUM*SLEN*32) / 256;
    const int  g_ln   = NTOK;

    // ---- weight splits (graph-captured; run every replay) ----
    split_kernel<<<(W_OUT1_OFF-W_IN1_OFF)/1024, blk>>>(w_in1,  WH+W_IN1_OFF,  WL+W_IN1_OFF);
    split_kernel<<<(W_IN2_OFF-W_OUT1_OFF)/1024, blk>>>(w_out1, WH+W_OUT1_OFF, WL+W_OUT1_OFF);
    split_kernel<<<(W_OUT2_OFF-W_IN2_OFF)/1024, blk>>>(w_in2,  WH+W_IN2_OFF,  WL+W_IN2_OFF);
    split_kernel<<<(FW1_OFF-W_OUT2_OFF)/1024, blk>>>(w_out2, WH+W_OUT2_OFF, WL+W_OUT2_OFF);
    split_kernel<<<(FW2_OFF-FW1_OFF)/1024, blk>>>(ffn_w1, WH+FW1_OFF,    WL+FW1_OFF);
    split_kernel<<<(WTOTAL-FW2_OFF)/1024, blk>>>(ffn_w2, WH+FW2_OFF,    WL+FW2_OFF);

    // initial activation split (layer-0 input)
    split_kernel<<<(NTOK*DDIM)/1024, blk>>>(x_in, P1H, P1L);

    const float* xcur = x_in;
    for (int l = 0; l < LNUM; l++) {
        const size_t oW3 = (size_t)l * D3 * DDIM;
        const size_t oW1 = (size_t)l * DDIM * DDIM;
        const size_t oWm = (size_t)l * MDIM * DDIM;

        // ---- intra-frame full MHA ----
        gemm_bf3<0,true,false><<<g_qkvp, blk, GSMEM_BYTES>>>(
            P1H, P1L, WH+W_IN1_OFF+oW3, WL+W_IN1_OFF+oW3,
            b_in1 + (size_t)l*D3, nullptr, nullptr, QKVH, QKVL, NTOK, D3, DDIM);
        attn_tc_kernel<<<g_attn, 128, ATTN_TC_SMEM>>>(QKVH, QKVL, P1H, P1L);
        gemm_bf3<0,false,true><<<g_outp, blk, GSMEM_BYTES>>>(
            P1H, P1L, WH+W_OUT1_OFF+oW1, WL+W_OUT1_OFF+oW1,
            b_out1 + (size_t)l*DDIM, nullptr, PROJ, nullptr, nullptr, NTOK, DDIM, DDIM);
        ln_kernel<<<g_ln, blk>>>(PROJ, xcur, ln1_g + (size_t)l*DDIM,
                                 ln1_b + (size_t)l*DDIM, X2, P1H, P1L);

        // ---- inter-frame banded MHA ----
        gemm_bf3<0,true,false><<<g_qkvp, blk, GSMEM_BYTES>>>(
            P1H, P1L, WH+W_IN2_OFF+oW3, WL+W_IN2_OFF+oW3,
            b_in2 + (size_t)l*D3, nullptr, nullptr, QKVH, QKVL, NTOK, D3, DDIM);
        attn_band_kernel<<<g_band, blk>>>(QKVH, QKVL, P1H, P1L);
        gemm_bf3<0,false,true><<<g_outp, blk, GSMEM_BYTES>>>(
            P1H, P1L, WH+W_OUT2_OFF+oW1, WL+W_OUT2_OFF+oW1,
            b_out2 + (size_t)l*DDIM, nullptr, PROJ, nullptr, nullptr, NTOK, DDIM, DDIM);
        ln_kernel<<<g_ln, blk>>>(PROJ, X2, ln2_g + (size_t)l*DDIM,
                                 ln2_b + (size_t)l*DDIM, ATT, P1H, P1L);

        // ---- FFN ----
        gemm_bf3<1,true,false><<<g_ffn1, blk, GSMEM_BYTES>>>(
            P1H, P1L, WH+FW1_OFF+oWm, WL+FW1_OFF+oWm,
            ffn_b1 + (size_t)l*MDIM, nullptr, nullptr, P2H, P2L, NTOK, MDIM, DDIM);
        gemm_bf3<2,true,true><<<g_outp, blk, GSMEM_BYTES>>>(
            P2H, P2L, WH+FW2_OFF+oWm, WL+FW2_OFF+oWm,
            ffn_b2 + (size_t)l*DDIM, ATT, X, P1H, P1L, NTOK, DDIM, MDIM);
        xcur = X;
    }

    ln_kernel<<<g_ln, blk>>>(xcur, nullptr, lnf_g, lnf_b, (float*)d_out,
                             nullptr, nullptr);
}

// round 6
// speedup vs baseline: 2.1734x; 1.0447x over previous
#include <cuda_runtime.h>
#include <cuda_bf16.h>
#include <math.h>
#include <stdint.h>

// ---------------------------------------------------------------------------
// Problem constants
// ---------------------------------------------------------------------------
#define LNUM 4
#define DDIM 1024
#define HNUM 16
#define HD   64
#define MDIM 4096
#define SLEN 1024
#define BNUM 2
#define NTOK (BNUM*SLEN)        // 2048
#define D3   (3*DDIM)           // 3072
#define EPS  1e-5f

// Weight split array layout (element offsets)
#define W_IN1_OFF   0u
#define W_OUT1_OFF  12582912u
#define W_IN2_OFF   16777216u
#define W_OUT2_OFF  29360128u
#define FW1_OFF     33554432u
#define FW2_OFF     50331648u
#define WTOTAL      67108864u

// ---------------------------------------------------------------------------
// Device scratch (no allocations allowed)
// ---------------------------------------------------------------------------
static __device__ float g_proj[NTOK*DDIM];
static __device__ float g_x   [NTOK*DDIM];
static __device__ float g_x2  [NTOK*DDIM];
static __device__ float g_att [NTOK*DDIM];

static __device__ __nv_bfloat16 g_wh[WTOTAL];        // weight hi
static __device__ __nv_bfloat16 g_wl[WTOTAL];        // weight lo
static __device__ __nv_bfloat16 g_qkvh[NTOK*D3];     // qkv hi
static __device__ __nv_bfloat16 g_qkvl[NTOK*D3];     // qkv lo
static __device__ __nv_bfloat16 g_p1h[NTOK*DDIM];
static __device__ __nv_bfloat16 g_p1l[NTOK*DDIM];
static __device__ __nv_bfloat16 g_p2h[NTOK*MDIM];
static __device__ __nv_bfloat16 g_p2l[NTOK*MDIM];

// ---------------------------------------------------------------------------
// Helpers
// ---------------------------------------------------------------------------
__device__ __forceinline__ void cp16(uint32_t d, const void* s) {
    asm volatile("cp.async.cg.shared.global [%0], [%1], 16;\n" :: "r"(d), "l"(s));
}
__device__ __forceinline__ void cp_commit() {
    asm volatile("cp.async.commit_group;\n" ::: "memory");
}
__device__ __forceinline__ void cp_wait1() {
    asm volatile("cp.async.wait_group 1;\n" ::: "memory");
}
__device__ __forceinline__ void cp_wait0() {
    asm volatile("cp.async.wait_group 0;\n" ::: "memory");
}
__device__ __forceinline__ void ldsm4(uint32_t* r, uint32_t a) {
    asm volatile("ldmatrix.sync.aligned.m8n8.x4.shared.b16 {%0,%1,%2,%3}, [%4];"
        : "=r"(r[0]), "=r"(r[1]), "=r"(r[2]), "=r"(r[3]) : "r"(a));
}
__device__ __forceinline__ void ldsm4t(uint32_t* r, uint32_t a) {
    asm volatile("ldmatrix.sync.aligned.m8n8.x4.trans.shared.b16 {%0,%1,%2,%3}, [%4];"
        : "=r"(r[0]), "=r"(r[1]), "=r"(r[2]), "=r"(r[3]) : "r"(a));
}
__device__ __forceinline__ void mma16816(float* c, const uint32_t* a,
                                         uint32_t b0, uint32_t b1) {
    asm volatile(
        "mma.sync.aligned.m16n8k16.row.col.f32.bf16.bf16.f32 "
        "{%0,%1,%2,%3},{%4,%5,%6,%7},{%8,%9},{%0,%1,%2,%3};"
        : "+f"(c[0]), "+f"(c[1]), "+f"(c[2]), "+f"(c[3])
        : "r"(a[0]), "r"(a[1]), "r"(a[2]), "r"(a[3]), "r"(b0), "r"(b1));
}
__device__ __forceinline__ uint32_t pack2(__nv_bfloat16 a, __nv_bfloat16 b) {
    __nv_bfloat162 t = __halves2bfloat162(a, b);
    return *reinterpret_cast<uint32_t*>(&t);
}
__device__ __forceinline__ void split1(float v, __nv_bfloat16& h, __nv_bfloat16& l) {
    h = __float2bfloat16(v);
    l = __float2bfloat16(v - __bfloat162float(h));
}
__device__ __forceinline__ float bf2f(__nv_bfloat16 v) { return __bfloat162float(v); }

// ---------------------------------------------------------------------------
// fp32 -> (hi,lo) bf16 split kernel. n must be a multiple of 1024.
// ---------------------------------------------------------------------------
__global__ __launch_bounds__(256)
void split_kernel(const float* __restrict__ in, __nv_bfloat16* __restrict__ hi,
                  __nv_bfloat16* __restrict__ lo)
{
    const size_t i = ((size_t)blockIdx.x * 256 + threadIdx.x) * 4;
    float4 v = *(const float4*)(in + i);
    __nv_bfloat16 h0,h1,h2,h3,l0,l1,l2,l3;
    split1(v.x,h0,l0); split1(v.y,h1,l1); split1(v.z,h2,l2); split1(v.w,h3,l3);
    uint2 uh; uh.x = pack2(h0,h1); uh.y = pack2(h2,h3);
    uint2 ul; ul.x = pack2(l0,l1); ul.y = pack2(l2,l3);
    *(uint2*)(hi + i) = uh;
    *(uint2*)(lo + i) = ul;
}

// ---------------------------------------------------------------------------
// bf16x3 tensor-core GEMM: C[M,N] = A[M,K] @ Bw[N,K]^T + bias (+ epilogue)
// A,B given as (hi,lo) bf16 pairs; product = Ah*Bh + Ah*Bl + Al*Bh (fp32 acc).
// CTA tile 128x128x32, 128 threads (4 warps, 64x64 warp tiles), cp.async
// 3-stage pipeline. EPI: 0=bias, 1=bias+GELU, 2=bias+residual.
// OSPLIT: write hi/lo bf16 outputs. OF32: write fp32 output.
// ---------------------------------------------------------------------------
#define STAGE_BYTES 32768
#define GSMEM_BYTES (3*STAGE_BYTES)

template<int EPI, bool OSPLIT, bool OF32>
__global__ __launch_bounds__(128)
void gemm_bf3(const __nv_bfloat16* __restrict__ Ah, const __nv_bfloat16* __restrict__ Al,
              const __nv_bfloat16* __restrict__ Bh, const __nv_bfloat16* __restrict__ Bl,
              const float* __restrict__ bias, const float* __restrict__ Res,
              float* __restrict__ C, __nv_bfloat16* __restrict__ Chi,
              __nv_bfloat16* __restrict__ Clo, int M, int N, int K)
{
    extern __shared__ __nv_bfloat16 smbuf[];
    const uint32_t smem_u32 = (uint32_t)__cvta_generic_to_shared(smbuf);

    const int tid = threadIdx.x;
    const int m0 = blockIdx.y * 128;
    const int n0 = blockIdx.x * 128;

    // ---- global->smem loader: each thread owns row `tid` of all 4 regions ----
    const __nv_bfloat16* pAh = Ah + (size_t)(m0 + tid) * K;
    const __nv_bfloat16* pAl = Al + (size_t)(m0 + tid) * K;
    const __nv_bfloat16* pBh = Bh + (size_t)(n0 + tid) * K;
    const __nv_bfloat16* pBl = Bl + (size_t)(n0 + tid) * K;
    const uint32_t rowb = (uint32_t)tid * 16;   // byte offset of row within ko-slab

    auto load_stage = [&](int kt, int s) {
        const uint32_t sb = smem_u32 + (uint32_t)s * STAGE_BYTES;
        const size_t gk = (size_t)kt * 32;
        #pragma unroll
        for (int ko = 0; ko < 4; ko++) {
            const uint32_t o = (uint32_t)ko * 2048 + rowb;
            cp16(sb + o,          pAh + gk + ko*8);
            cp16(sb + 8192  + o,  pAl + gk + ko*8);
            cp16(sb + 16384 + o,  pBh + gk + ko*8);
            cp16(sb + 24576 + o,  pBl + gk + ko*8);
        }
        cp_commit();
    };

    // ---- warp/frag mapping: 4 warps, 2x2, warp tile 64x64 ----
    const int wid  = tid >> 5;
    const int lane = tid & 31;
    const int wm = (wid >> 1) * 64;       // 0 or 64
    const int wn = (wid & 1) * 64;        // 0 or 64
    const int a_row = lane & 15;
    const int a_ko  = lane >> 4;                           // 0..1
    const int b_row = (lane & 7) + ((lane & 16) >> 1);     // +8 for upper half
    const int b_ko  = (lane >> 3) & 1;

    const uint32_t aoff = (uint32_t)((a_ko*1024 + (wm + a_row)*8) * 2);
    const uint32_t boff = (uint32_t)((b_ko*1024 + (wn + b_row)*8) * 2);

    float acc[4][8][4];
    #pragma unroll
    for (int i = 0; i < 4; i++)
        #pragma unroll
        for (int j = 0; j < 8; j++)
            #pragma unroll
            for (int e = 0; e < 4; e++) acc[i][j][e] = 0.f;

    const int T = K >> 5;

    load_stage(0, 0);
    if (T > 1) load_stage(1, 1);

    for (int kt = 0; kt < T; kt++) {
        if (kt + 1 < T) cp_wait1(); else cp_wait0();
        __syncthreads();
        // prefetch stage kt+2 into the buffer freed by iteration kt-1
        if (kt + 2 < T) load_stage(kt + 2, (kt + 2) % 3);

        const uint32_t sb = smem_u32 + (uint32_t)(kt % 3) * STAGE_BYTES;
        #pragma unroll
        for (int ko0 = 0; ko0 < 4; ko0 += 2) {
            uint32_t a_h[4][4], a_l[4][4], b_h[16], b_l[16];
            #pragma unroll
            for (int mf = 0; mf < 4; mf++) {
                const uint32_t ad = sb + aoff + (uint32_t)ko0*2048 + (uint32_t)mf*256;
                ldsm4(a_h[mf], ad);
                ldsm4(a_l[mf], ad + 8192);
            }
            #pragma unroll
            for (int nf2 = 0; nf2 < 4; nf2++) {
                const uint32_t bd = sb + 16384 + boff + (uint32_t)ko0*2048 + (uint32_t)nf2*256;
                ldsm4(&b_h[nf2*4], bd);
                ldsm4(&b_l[nf2*4], bd + 8192);
            }
            #pragma unroll
            for (int mf = 0; mf < 4; mf++)
                #pragma unroll
                for (int nf = 0; nf < 8; nf++) {
                    mma16816(acc[mf][nf], a_h[mf], b_h[nf*2], b_h[nf*2+1]);
                    mma16816(acc[mf][nf], a_h[mf], b_l[nf*2], b_l[nf*2+1]);
                    mma16816(acc[mf][nf], a_l[mf], b_h[nf*2], b_h[nf*2+1]);
                }
        }
        __syncthreads();
    }

    // ---- epilogue ----
    const int er = lane >> 2;
    const int ec = (lane & 3) * 2;
    #pragma unroll
    for (int mf = 0; mf < 4; mf++) {
        #pragma unroll
        for (int nf = 0; nf < 8; nf++) {
            const int m = m0 + wm + mf*16 + er;
            const int n = n0 + wn + nf*8 + ec;
            const float2 bv = *(const float2*)(bias + n);
            #pragma unroll
            for (int half = 0; half < 2; half++) {
                const int mm = m + half*8;
                float t0 = acc[mf][nf][half*2+0] + bv.x;
                float t1 = acc[mf][nf][half*2+1] + bv.y;
                if (EPI == 1) {
                    t0 = 0.5f * t0 * (1.f + erff(t0 * 0.70710678118654752f));
                    t1 = 0.5f * t1 * (1.f + erff(t1 * 0.70710678118654752f));
                }
                if (EPI == 2) {
                    const float2 rv = *(const float2*)(Res + (size_t)mm * N + n);
                    t0 += rv.x; t1 += rv.y;
                }
                if (OF32) {
                    *(float2*)(C + (size_t)mm * N + n) = make_float2(t0, t1);
                }
                if (OSPLIT) {
                    __nv_bfloat16 h0,h1,l0,l1;
                    split1(t0,h0,l0); split1(t1,h1,l1);
                    *(uint32_t*)(Chi + (size_t)mm * N + n) = pack2(h0,h1);
                    *(uint32_t*)(Clo + (size_t)mm * N + n) = pack2(l0,l1);
                }
            }
        }
    }
}

// ---------------------------------------------------------------------------
// Tensor-core full attention (bf16x3 flash) — unchanged from round 4.
// ---------------------------------------------------------------------------
#define ATTN_TC_SMEM 81920

__global__ __launch_bounds__(128)
void attn_tc_kernel(const __nv_bfloat16* __restrict__ qkvh,
                    const __nv_bfloat16* __restrict__ qkvl,
                    __nv_bfloat16* __restrict__ oh,
                    __nv_bfloat16* __restrict__ ol)
{
    extern __shared__ char smc[];
    const uint32_t sb = (uint32_t)__cvta_generic_to_shared(smc);

    const int bh = blockIdx.x;
    const int b  = bh >> 4;
    const int h  = bh & 15;
    const int qt = blockIdx.y;
    const int tid  = threadIdx.x;
    const int wid  = tid >> 5;
    const int lane = tid & 31;

    const int r    = tid >> 1;
    const int koh  = (tid & 1) * 4;

    {
        const size_t qrow = (size_t)(b*SLEN + qt*64 + r) * D3 + h*HD;
        #pragma unroll
        for (int it = 0; it < 4; it++) {
            const int ko = koh + it;
            const uint32_t dst = sb + (uint32_t)(((ko*64 + r)*8) * 2);
            cp16(dst,        qkvh + qrow + ko*8);
            cp16(dst + 8192, qkvl + qrow + ko*8);
        }
    }

    auto load_kv = [&](int kt, int s) {
        const uint32_t stg = sb + 16384 + (uint32_t)s * 32768;
        const size_t krow = (size_t)(b*SLEN + kt*64 + r) * D3 + DDIM + h*HD;
        const size_t vrow = krow + DDIM;
        #pragma unroll
        for (int it = 0; it < 4; it++) {
            const int ko = koh + it;
            const uint32_t off = (uint32_t)(((ko*64 + r)*8) * 2);
            cp16(stg + off,          qkvh + krow + ko*8);
            cp16(stg + 8192  + off,  qkvl + krow + ko*8);
            cp16(stg + 16384 + off,  qkvh + vrow + ko*8);
            cp16(stg + 24576 + off,  qkvl + vrow + ko*8);
        }
    };

    load_kv(0, 0);
    cp_commit();

    const int a_row = lane & 15;
    const int a_ko  = lane >> 4;
    const int b_row = (lane & 7) + ((lane & 16) >> 1);
    const int b_ko  = (lane >> 3) & 1;
    const int v_key = lane & 15;
    const int v_ko  = lane >> 4;

    uint32_t qa_h[4][4], qa_l[4][4];

    float m0 = -1e30f, m1 = -1e30f, l0 = 0.f, l1 = 0.f;
    float oacc[8][4];
    #pragma unroll
    for (int nf = 0; nf < 8; nf++)
        #pragma unroll
        for (int e = 0; e < 4; e++) oacc[nf][e] = 0.f;

    for (int kt = 0; kt < 16; kt++) {
        const int s = kt & 1;
        if (kt + 1 < 16) {
            load_kv(kt + 1, s ^ 1);
            cp_commit();
            cp_wait1();
        } else {
            cp_wait0();
        }
        __syncthreads();

        if (kt == 0) {
            #pragma unroll
            for (int ks = 0; ks < 4; ks++) {
                const uint32_t ad = sb +
                    (uint32_t)((((ks*2 + a_ko)*64 + wid*16 + a_row)*8) * 2);
                ldsm4(qa_h[ks], ad);
                ldsm4(qa_l[ks], ad + 8192);
            }
        }

        const uint32_t stg = sb + 16384 + (uint32_t)s * 32768;

        float sc[8][4];
        #pragma unroll
        for (int nf = 0; nf < 8; nf++)
            #pragma unroll
            for (int e = 0; e < 4; e++) sc[nf][e] = 0.f;

        #pragma unroll
        for (int ks = 0; ks < 4; ks++) {
            #pragma unroll
            for (int np = 0; np < 4; np++) {
                uint32_t kb[4], kl[4];
                const uint32_t kd = stg +
                    (uint32_t)((((ks*2 + b_ko)*64 + np*16 + b_row)*8) * 2);
                ldsm4(kb, kd);
                ldsm4(kl, kd + 8192);
                mma16816(sc[2*np],   qa_h[ks], kb[0], kb[1]);
                mma16816(sc[2*np],   qa_h[ks], kl[0], kl[1]);
                mma16816(sc[2*np],   qa_l[ks], kb[0], kb[1]);
                mma16816(sc[2*np+1], qa_h[ks], kb[2], kb[3]);
                mma16816(sc[2*np+1], qa_h[ks], kl[2], kl[3]);
                mma16816(sc[2*np+1], qa_l[ks], kb[2], kb[3]);
            }
        }

        #pragma unroll
        for (int nf = 0; nf < 8; nf++)
            #pragma unroll
            for (int e = 0; e < 4; e++) sc[nf][e] *= 0.125f;

        float mx0 = m0, mx1 = m1;
        #pragma unroll
        for (int nf = 0; nf < 8; nf++) {
            mx0 = fmaxf(mx0, fmaxf(sc[nf][0], sc[nf][1]));
            mx1 = fmaxf(mx1, fmaxf(sc[nf][2], sc[nf][3]));
        }
        mx0 = fmaxf(mx0, __shfl_xor_sync(0xffffffffu, mx0, 1));
        mx0 = fmaxf(mx0, __shfl_xor_sync(0xffffffffu, mx0, 2));
        mx1 = fmaxf(mx1, __shfl_xor_sync(0xffffffffu, mx1, 1));
        mx1 = fmaxf(mx1, __shfl_xor_sync(0xffffffffu, mx1, 2));

        const float al0 = __expf(m0 - mx0);
        const float al1 = __expf(m1 - mx1);
        m0 = mx0; m1 = mx1;

        float s0 = 0.f, s1 = 0.f;
        uint32_t pah[4][4], pal[4][4];
        #pragma unroll
        for (int nf = 0; nf < 8; nf++) {
            const float p0 = __expf(sc[nf][0] - m0);
            const float p1 = __expf(sc[nf][1] - m0);
            const float p2 = __expf(sc[nf][2] - m1);
            const float p3 = __expf(sc[nf][3] - m1);
            s0 += p0 + p1;
            s1 += p2 + p3;
            __nv_bfloat16 h0,h1,h2,h3,lo0,lo1,lo2,lo3;
            split1(p0,h0,lo0); split1(p1,h1,lo1);
            split1(p2,h2,lo2); split1(p3,h3,lo3);
            const int ks = nf >> 1;
            const int hv = (nf & 1) * 2;
            pah[ks][hv+0] = pack2(h0, h1);
            pah[ks][hv+1] = pack2(h2, h3);
            pal[ks][hv+0] = pack2(lo0, lo1);
            pal[ks][hv+1] = pack2(lo2, lo3);
        }
        s0 += __shfl_xor_sync(0xffffffffu, s0, 1);
        s0 += __shfl_xor_sync(0xffffffffu, s0, 2);
        s1 += __shfl_xor_sync(0xffffffffu, s1, 1);
        s1 += __shfl_xor_sync(0xffffffffu, s1, 2);
        l0 = l0 * al0 + s0;
        l1 = l1 * al1 + s1;

        #pragma unroll
        for (int nf = 0; nf < 8; nf++) {
            oacc[nf][0] *= al0; oacc[nf][1] *= al0;
            oacc[nf][2] *= al1; oacc[nf][3] *= al1;
        }

        #pragma unroll
        for (int ks = 0; ks < 4; ks++) {
            #pragma unroll
            for (int np = 0; np < 4; np++) {
                uint32_t vb[4], vl[4];
                const uint32_t vd = stg + 16384 +
                    (uint32_t)((((np*2 + v_ko)*64 + ks*16 + v_key)*8) * 2);
                ldsm4t(vb, vd);
                ldsm4t(vl, vd + 8192);
                mma16816(oacc[2*np],   pah[ks], vb[0], vb[1]);
                mma16816(oacc[2*np],   pah[ks], vl[0], vl[1]);
                mma16816(oacc[2*np],   pal[ks], vb[0], vb[1]);
                mma16816(oacc[2*np+1], pah[ks], vb[2], vb[3]);
                mma16816(oacc[2*np+1], pah[ks], vl[2], vl[3]);
                mma16816(oacc[2*np+1], pal[ks], vb[2], vb[3]);
            }
        }
        __syncthreads();
    }

    const float inv0 = 1.f / l0;
    const float inv1 = 1.f / l1;
    const int er  = lane >> 2;
    const int ec  = (lane & 3) * 2;
    const int tok0 = b*SLEN + qt*64 + wid*16 + er;
    const int tok1 = tok0 + 8;
    #pragma unroll
    for (int nf = 0; nf < 8; nf++) {
        const int col = h*HD + nf*8 + ec;
        const float o0 = oacc[nf][0] * inv0;
        const float o1 = oacc[nf][1] * inv0;
        const float o2 = oacc[nf][2] * inv1;
        const float o3 = oacc[nf][3] * inv1;
        __nv_bfloat16 h0,h1,h2,h3,lo0,lo1,lo2,lo3;
        split1(o0,h0,lo0); split1(o1,h1,lo1);
        split1(o2,h2,lo2); split1(o3,h3,lo3);
        *(uint32_t*)(oh + (size_t)tok0 * DDIM + col) = pack2(h0, h1);
        *(uint32_t*)(ol + (size_t)tok0 * DDIM + col) = pack2(lo0, lo1);
        *(uint32_t*)(oh + (size_t)tok1 * DDIM + col) = pack2(h2, h3);
        *(uint32_t*)(ol + (size_t)tok1 * DDIM + col) = pack2(lo2, lo3);
    }
}

// ---------------------------------------------------------------------------
// Banded attention — unchanged from round 4.
// ---------------------------------------------------------------------------
__global__ __launch_bounds__(256)
void attn_band_kernel(const __nv_bfloat16* __restrict__ qkvh,
                      const __nv_bfloat16* __restrict__ qkvl,
                      __nv_bfloat16* __restrict__ oh,
                      __nv_bfloat16* __restrict__ ol)
{
    const int gw   = (blockIdx.x * blockDim.x + threadIdx.x) >> 5;
    const int lane = threadIdx.x & 31;
    const int i = gw & (SLEN-1);
    const int h = (gw >> 10) & (HNUM-1);
    const int b = gw >> 14;

    const size_t qbase = (size_t)(b*SLEN + i) * D3 + h*HD;
    const float q0 = bf2f(qkvh[qbase + lane])      + bf2f(qkvl[qbase + lane]);
    const float q1 = bf2f(qkvh[qbase + 32 + lane]) + bf2f(qkvl[qbase + 32 + lane]);

    float sc[5];
    int   jc[5];
    #pragma unroll
    for (int jj = 0; jj < 5; jj++) {
        int j = i - 2 + jj;
        bool valid = (j >= 0) && (j < SLEN);
        jc[jj] = valid ? j : i;
        const size_t kb = (size_t)(b*SLEN + jc[jj]) * D3 + DDIM + h*HD;
        const float k0 = bf2f(qkvh[kb + lane])      + bf2f(qkvl[kb + lane]);
        const float k1 = bf2f(qkvh[kb + 32 + lane]) + bf2f(qkvl[kb + 32 + lane]);
        float p = q0 * k0 + q1 * k1;
        #pragma unroll
        for (int off = 16; off; off >>= 1) p += __shfl_xor_sync(0xffffffffu, p, off);
        sc[jj] = valid ? p * 0.125f : -1e30f;
    }
    float mx = sc[0];
    #pragma unroll
    for (int jj = 1; jj < 5; jj++) mx = fmaxf(mx, sc[jj]);
    float w[5], sum = 0.f;
    #pragma unroll
    for (int jj = 0; jj < 5; jj++) { w[jj] = __expf(sc[jj] - mx); sum += w[jj]; }
    const float inv = 1.f / sum;

    float o0 = 0.f, o1 = 0.f;
    #pragma unroll
    for (int jj = 0; jj < 5; jj++) {
        const size_t vb = (size_t)(b*SLEN + jc[jj]) * D3 + 2*DDIM + h*HD;
        const float v0 = bf2f(qkvh[vb + lane])      + bf2f(qkvl[vb + lane]);
        const float v1 = bf2f(qkvh[vb + 32 + lane]) + bf2f(qkvl[vb + 32 + lane]);
        o0 = fmaf(w[jj], v0, o0);
        o1 = fmaf(w[jj], v1, o1);
    }
    o0 *= inv; o1 *= inv;

    const size_t ob = (size_t)(b*SLEN + i) * DDIM + h*HD;
    __nv_bfloat16 hh, ll;
    split1(o0, hh, ll);
    oh[ob + lane] = hh;  ol[ob + lane] = ll;
    split1(o1, hh, ll);
    oh[ob + 32 + lane] = hh;  ol[ob + 32 + lane] = ll;
}

// ---------------------------------------------------------------------------
// LayerNorm — unchanged from round 4.
// ---------------------------------------------------------------------------
__global__ __launch_bounds__(256)
void ln_kernel(const float* __restrict__ a, const float* __restrict__ r,
               const float* __restrict__ g, const float* __restrict__ bt,
               float* __restrict__ out,
               __nv_bfloat16* __restrict__ ohh, __nv_bfloat16* __restrict__ oll)
{
    __shared__ float red[2][8];
    __shared__ float s_mean, s_rstd;
    const int n = blockIdx.x;
    const int tid = threadIdx.x;
    const size_t base = (size_t)n * DDIM + tid * 4;

    float4 va = *(const float4*)(a + base);
    if (r) {
        float4 vr = *(const float4*)(r + base);
        va.x += vr.x; va.y += vr.y; va.z += vr.z; va.w += vr.w;
    }
    float s  = va.x + va.y + va.z + va.w;
    float sq = va.x*va.x + va.y*va.y + va.z*va.z + va.w*va.w;

    #pragma unroll
    for (int off = 16; off; off >>= 1) {
        s  += __shfl_xor_sync(0xffffffffu, s,  off);
        sq += __shfl_xor_sync(0xffffffffu, sq, off);
    }
    const int wid = tid >> 5;
    if ((tid & 31) == 0) { red[0][wid] = s; red[1][wid] = sq; }
    __syncthreads();
    if (tid < 32) {
        float ts  = (tid < 8) ? red[0][tid] : 0.f;
        float tsq = (tid < 8) ? red[1][tid] : 0.f;
        #pragma unroll
        for (int off = 4; off; off >>= 1) {
            ts  += __shfl_xor_sync(0xffffffffu, ts,  off);
            tsq += __shfl_xor_sync(0xffffffffu, tsq, off);
        }
        if (tid == 0) {
            float mean = ts * (1.f / DDIM);
            float var  = tsq * (1.f / DDIM) - mean * mean;
            s_mean = mean;
            s_rstd = rsqrtf(var + EPS);
        }
    }
    __syncthreads();
    const float mean = s_mean, rstd = s_rstd;
    float4 gg = *(const float4*)(g + tid*4);
    float4 bb = *(const float4*)(bt + tid*4);
    float4 o;
    o.x = (va.x - mean) * rstd * gg.x + bb.x;
    o.y = (va.y - mean) * rstd * gg.y + bb.y;
    o.z = (va.z - mean) * rstd * gg.z + bb.z;
    o.w = (va.w - mean) * rstd * gg.w + bb.w;
    *(float4*)(out + base) = o;
    if (ohh) {
        __nv_bfloat16 h0,h1,h2,h3,l0,l1,l2,l3;
        split1(o.x,h0,l0); split1(o.y,h1,l1); split1(o.z,h2,l2); split1(o.w,h3,l3);
        uint2 uh; uh.x = pack2(h0,h1); uh.y = pack2(h2,h3);
        uint2 ul; ul.x = pack2(l0,l1); ul.y = pack2(l2,l3);
        *(uint2*)(ohh + base) = uh;
        *(uint2*)(oll + base) = ul;
    }
}

// ---------------------------------------------------------------------------
// Orchestration
// ---------------------------------------------------------------------------
extern "C" void kernel_launch(void* const* d_in, const int* in_sizes, int n_in,
                              void* d_out, int out_size)
{
    const float* x_in   = (const float*)d_in[0];
    const float* w_in1  = (const float*)d_in[1];
    const float* b_in1  = (const float*)d_in[2];
    const float* w_out1 = (const float*)d_in[3];
    const float* b_out1 = (const float*)d_in[4];
    const float* ln1_g  = (const float*)d_in[5];
    const float* ln1_b  = (const float*)d_in[6];
    const float* w_in2  = (const float*)d_in[7];
    const float* b_in2  = (const float*)d_in[8];
    const float* w_out2 = (const float*)d_in[9];
    const float* b_out2 = (const float*)d_in[10];
    const float* ln2_g  = (const float*)d_in[11];
    const float* ln2_b  = (const float*)d_in[12];
    const float* ffn_w1 = (const float*)d_in[13];
    const float* ffn_b1 = (const float*)d_in[14];
    const float* ffn_w2 = (const float*)d_in[15];
    const float* ffn_b2 = (const float*)d_in[16];
    const float* lnf_g  = (const float*)d_in[17];
    const float* lnf_b  = (const float*)d_in[18];

    float *PROJ, *X, *X2, *ATT;
    __nv_bfloat16 *WH, *WL, *QKVH, *QKVL, *P1H, *P1L, *P2H, *P2L;
    cudaGetSymbolAddress((void**)&PROJ, g_proj);
    cudaGetSymbolAddress((void**)&X,    g_x);
    cudaGetSymbolAddress((void**)&X2,   g_x2);
    cudaGetSymbolAddress((void**)&ATT,  g_att);
    cudaGetSymbolAddress((void**)&WH,   g_wh);
    cudaGetSymbolAddress((void**)&WL,   g_wl);
    cudaGetSymbolAddress((void**)&QKVH, g_qkvh);
    cudaGetSymbolAddress((void**)&QKVL, g_qkvl);
    cudaGetSymbolAddress((void**)&P1H,  g_p1h);
    cudaGetSymbolAddress((void**)&P1L,  g_p1l);
    cudaGetSymbolAddress((void**)&P2H,  g_p2h);
    cudaGetSymbolAddress((void**)&P2L,  g_p2l);

    cudaFuncSetAttribute(attn_tc_kernel,
                         cudaFuncAttributeMaxDynamicSharedMemorySize, ATTN_TC_SMEM);
    cudaFuncSetAttribute(gemm_bf3<0,false,true>,
                         cudaFuncAttributeMaxDynamicSharedMemorySize, GSMEM_BYTES);
    cudaFuncSetAttribute(gemm_bf3<0,true,false>,
                         cudaFuncAttributeMaxDynamicSharedMemorySize, GSMEM_BYTES);
    cudaFuncSetAttribute(gemm_bf3<1,true,false>,
                         cudaFuncAttributeMaxDynamicSharedMemorySize, GSMEM_BYTES);
    cudaFuncSetAttribute(gemm_bf3<2,true,true>,
                         cudaFuncAttributeMaxDynamicSharedMemorySize, GSMEM_BYTES);

    const dim3 blk(256);
    const dim3 gblk(128);
    const dim3 g_qkvp(D3/128,  NTOK/128);   // (24,16)
    const dim3 g_outp(DDIM/128, NTOK/128);  // (8,16)
    const dim3 g_ffn1(MDIM/128, NTOK/128);  // (32,16)
    const dim3 g_attn(BNUM*HNUM, SLEN/64);  // (32,16)
    const int  g_band = (BNUM*HNUM*SLEN*32) / 256;
    const int  g_ln   = NTOK;

    // ---- weight splits (graph-captured; run every replay) ----
    split_kernel<<<(W_OUT1_OFF-W_IN1_OFF)/1024, blk>>>(w_in1,  WH+W_IN1_OFF,  WL+W_IN1_OFF);
    split_kernel<<<(W_IN2_OFF-W_OUT1_OFF)/1024, blk>>>(w_out1, WH+W_OUT1_OFF, WL+W_OUT1_OFF);
    split_kernel<<<(W_OUT2_OFF-W_IN2_OFF)/1024, blk>>>(w_in2,  WH+W_IN2_OFF,  WL+W_IN2_OFF);
    split_kernel<<<(FW1_OFF-W_OUT2_OFF)/1024, blk>>>(w_out2, WH+W_OUT2_OFF, WL+W_OUT2_OFF);
    split_kernel<<<(FW2_OFF-FW1_OFF)/1024, blk>>>(ffn_w1, WH+FW1_OFF,    WL+FW1_OFF);
    split_kernel<<<(WTOTAL-FW2_OFF)/1024, blk>>>(ffn_w2, WH+FW2_OFF,    WL+FW2_OFF);

    // initial activation split (layer-0 input)
    split_kernel<<<(NTOK*DDIM)/1024, blk>>>(x_in, P1H, P1L);

    const float* xcur = x_in;
    for (int l = 0; l < LNUM; l++) {
        const size_t oW3 = (size_t)l * D3 * DDIM;
        const size_t oW1 = (size_t)l * DDIM * DDIM;
        const size_t oWm = (size_t)l * MDIM * DDIM;

        // ---- intra-frame full MHA ----
        gemm_bf3<0,true,false><<<g_qkvp, gblk, GSMEM_BYTES>>>(
            P1H, P1L, WH+W_IN1_OFF+oW3, WL+W_IN1_OFF+oW3,
            b_in1 + (size_t)l*D3, nullptr, nullptr, QKVH, QKVL, NTOK, D3, DDIM);
        attn_tc_kernel<<<g_attn, 128, ATTN_TC_SMEM>>>(QKVH, QKVL, P1H, P1L);
        gemm_bf3<0,false,true><<<g_outp, gblk, GSMEM_BYTES>>>(
            P1H, P1L, WH+W_OUT1_OFF+oW1, WL+W_OUT1_OFF+oW1,
            b_out1 + (size_t)l*DDIM, nullptr, PROJ, nullptr, nullptr, NTOK, DDIM, DDIM);
        ln_kernel<<<g_ln, blk>>>(PROJ, xcur, ln1_g + (size_t)l*DDIM,
                                 ln1_b + (size_t)l*DDIM, X2, P1H, P1L);

        // ---- inter-frame banded MHA ----
        gemm_bf3<0,true,false><<<g_qkvp, gblk, GSMEM_BYTES>>>(
            P1H, P1L, WH+W_IN2_OFF+oW3, WL+W_IN2_OFF+oW3,
            b_in2 + (size_t)l*D3, nullptr, nullptr, QKVH, QKVL, NTOK, D3, DDIM);
        attn_band_kernel<<<g_band, blk>>>(QKVH, QKVL, P1H, P1L);
        gemm_bf3<0,false,true><<<g_outp, gblk, GSMEM_BYTES>>>(
            P1H, P1L, WH+W_OUT2_OFF+oW1, WL+W_OUT2_OFF+oW1,
            b_out2 + (size_t)l*DDIM, nullptr, PROJ, nullptr, nullptr, NTOK, DDIM, DDIM);
        ln_kernel<<<g_ln, blk>>>(PROJ, X2, ln2_g + (size_t)l*DDIM,
                                 ln2_b + (size_t)l*DDIM, ATT, P1H, P1L);

        // ---- FFN ----
        gemm_bf3<1,true,false><<<g_ffn1, gblk, GSMEM_BYTES>>>(
            P1H, P1L, WH+FW1_OFF+oWm, WL+FW1_OFF+oWm,
            ffn_b1 + (size_t)l*MDIM, nullptr, nullptr, P2H, P2L, NTOK, MDIM, DDIM);
        gemm_bf3<2,true,true><<<g_outp, gblk, GSMEM_BYTES>>>(
            P2H, P2L, WH+FW2_OFF+oWm, WL+FW2_OFF+oWm,
            ffn_b2 + (size_t)l*DDIM, ATT, X, P1H, P1L, NTOK, DDIM, MDIM);
        xcur = X;
    }

    ln_kernel<<<g_ln, blk>>>(xcur, nullptr, lnf_g, lnf_b, (float*)d_out,
                             nullptr, nullptr);
}

// round 7
// speedup vs baseline: 2.1905x; 1.0079x over previous
#include <cuda_runtime.h>
#include <cuda_bf16.h>
#include <math.h>
#include <stdint.h>

// ---------------------------------------------------------------------------
// Problem constants
// ---------------------------------------------------------------------------
#define LNUM 4
#define DDIM 1024
#define HNUM 16
#define HD   64
#define MDIM 4096
#define SLEN 1024
#define BNUM 2
#define NTOK (BNUM*SLEN)        // 2048
#define D3   (3*DDIM)           // 3072
#define EPS  1e-5f

// Weight split array layout (element offsets)
#define W_IN1_OFF   0u
#define W_OUT1_OFF  12582912u
#define W_IN2_OFF   16777216u
#define W_OUT2_OFF  29360128u
#define FW1_OFF     33554432u
#define FW2_OFF     50331648u
#define WTOTAL      67108864u

// ---------------------------------------------------------------------------
// Device scratch (no allocations allowed)
// ---------------------------------------------------------------------------
static __device__ float g_proj[NTOK*DDIM];
static __device__ float g_x   [NTOK*DDIM];
static __device__ float g_x2  [NTOK*DDIM];
static __device__ float g_att [NTOK*DDIM];

static __device__ __nv_bfloat16 g_wh[WTOTAL];        // weight hi
static __device__ __nv_bfloat16 g_wl[WTOTAL];        // weight lo
static __device__ __nv_bfloat16 g_qkvh[NTOK*D3];     // qkv hi
static __device__ __nv_bfloat16 g_qkvl[NTOK*D3];     // qkv lo
static __device__ __nv_bfloat16 g_p1h[NTOK*DDIM];
static __device__ __nv_bfloat16 g_p1l[NTOK*DDIM];
static __device__ __nv_bfloat16 g_p2h[NTOK*MDIM];
static __device__ __nv_bfloat16 g_p2l[NTOK*MDIM];

// ---------------------------------------------------------------------------
// Helpers
// ---------------------------------------------------------------------------
__device__ __forceinline__ void cp16(uint32_t d, const void* s) {
    asm volatile("cp.async.cg.shared.global [%0], [%1], 16;\n" :: "r"(d), "l"(s));
}
__device__ __forceinline__ void cp_commit() {
    asm volatile("cp.async.commit_group;\n" ::: "memory");
}
__device__ __forceinline__ void cp_wait1() {
    asm volatile("cp.async.wait_group 1;\n" ::: "memory");
}
__device__ __forceinline__ void cp_wait0() {
    asm volatile("cp.async.wait_group 0;\n" ::: "memory");
}
__device__ __forceinline__ void ldsm4(uint32_t* r, uint32_t a) {
    asm volatile("ldmatrix.sync.aligned.m8n8.x4.shared.b16 {%0,%1,%2,%3}, [%4];"
        : "=r"(r[0]), "=r"(r[1]), "=r"(r[2]), "=r"(r[3]) : "r"(a));
}
__device__ __forceinline__ void ldsm4t(uint32_t* r, uint32_t a) {
    asm volatile("ldmatrix.sync.aligned.m8n8.x4.trans.shared.b16 {%0,%1,%2,%3}, [%4];"
        : "=r"(r[0]), "=r"(r[1]), "=r"(r[2]), "=r"(r[3]) : "r"(a));
}
__device__ __forceinline__ void mma16816(float* c, const uint32_t* a,
                                         uint32_t b0, uint32_t b1) {
    asm volatile(
        "mma.sync.aligned.m16n8k16.row.col.f32.bf16.bf16.f32 "
        "{%0,%1,%2,%3},{%4,%5,%6,%7},{%8,%9},{%0,%1,%2,%3};"
        : "+f"(c[0]), "+f"(c[1]), "+f"(c[2]), "+f"(c[3])
        : "r"(a[0]), "r"(a[1]), "r"(a[2]), "r"(a[3]), "r"(b0), "r"(b1));
}
__device__ __forceinline__ uint32_t pack2(__nv_bfloat16 a, __nv_bfloat16 b) {
    __nv_bfloat162 t = __halves2bfloat162(a, b);
    return *reinterpret_cast<uint32_t*>(&t);
}
__device__ __forceinline__ void split1(float v, __nv_bfloat16& h, __nv_bfloat16& l) {
    h = __float2bfloat16(v);
    l = __float2bfloat16(v - __bfloat162float(h));
}
__device__ __forceinline__ float bf2f(__nv_bfloat16 v) { return __bfloat162float(v); }

// ---------------------------------------------------------------------------
// fp32 -> (hi,lo) bf16 split kernel. n must be a multiple of 4096.
// Each thread handles 4 independent float4s (MLP=4).
// ---------------------------------------------------------------------------
__global__ __launch_bounds__(256)
void split_kernel(const float* __restrict__ in, __nv_bfloat16* __restrict__ hi,
                  __nv_bfloat16* __restrict__ lo)
{
    const size_t base = (size_t)blockIdx.x * 4096 + threadIdx.x * 4;
    float4 v[4];
    #pragma unroll
    for (int j = 0; j < 4; j++)
        v[j] = *(const float4*)(in + base + j * 1024);
    #pragma unroll
    for (int j = 0; j < 4; j++) {
        const size_t i = base + j * 1024;
        __nv_bfloat16 h0,h1,h2,h3,l0,l1,l2,l3;
        split1(v[j].x,h0,l0); split1(v[j].y,h1,l1);
        split1(v[j].z,h2,l2); split1(v[j].w,h3,l3);
        uint2 uh; uh.x = pack2(h0,h1); uh.y = pack2(h2,h3);
        uint2 ul; ul.x = pack2(l0,l1); ul.y = pack2(l2,l3);
        *(uint2*)(hi + i) = uh;
        *(uint2*)(lo + i) = ul;
    }
}

// ---------------------------------------------------------------------------
// bf16x3 tensor-core GEMM (unchanged from round 6, known good).
// CTA tile 128x128x32, 128 threads (4 warps, 64x64 warp tiles), cp.async
// 3-stage pipeline. EPI: 0=bias, 1=bias+GELU, 2=bias+residual.
// ---------------------------------------------------------------------------
#define STAGE_BYTES 32768
#define GSMEM_BYTES (3*STAGE_BYTES)

template<int EPI, bool OSPLIT, bool OF32>
__global__ __launch_bounds__(128)
void gemm_bf3(const __nv_bfloat16* __restrict__ Ah, const __nv_bfloat16* __restrict__ Al,
              const __nv_bfloat16* __restrict__ Bh, const __nv_bfloat16* __restrict__ Bl,
              const float* __restrict__ bias, const float* __restrict__ Res,
              float* __restrict__ C, __nv_bfloat16* __restrict__ Chi,
              __nv_bfloat16* __restrict__ Clo, int M, int N, int K)
{
    extern __shared__ __nv_bfloat16 smbuf[];
    const uint32_t smem_u32 = (uint32_t)__cvta_generic_to_shared(smbuf);

    const int tid = threadIdx.x;
    const int m0 = blockIdx.y * 128;
    const int n0 = blockIdx.x * 128;

    const __nv_bfloat16* pAh = Ah + (size_t)(m0 + tid) * K;
    const __nv_bfloat16* pAl = Al + (size_t)(m0 + tid) * K;
    const __nv_bfloat16* pBh = Bh + (size_t)(n0 + tid) * K;
    const __nv_bfloat16* pBl = Bl + (size_t)(n0 + tid) * K;
    const uint32_t rowb = (uint32_t)tid * 16;

    auto load_stage = [&](int kt, int s) {
        const uint32_t sb = smem_u32 + (uint32_t)s * STAGE_BYTES;
        const size_t gk = (size_t)kt * 32;
        #pragma unroll
        for (int ko = 0; ko < 4; ko++) {
            const uint32_t o = (uint32_t)ko * 2048 + rowb;
            cp16(sb + o,          pAh + gk + ko*8);
            cp16(sb + 8192  + o,  pAl + gk + ko*8);
            cp16(sb + 16384 + o,  pBh + gk + ko*8);
            cp16(sb + 24576 + o,  pBl + gk + ko*8);
        }
        cp_commit();
    };

    const int wid  = tid >> 5;
    const int lane = tid & 31;
    const int wm = (wid >> 1) * 64;
    const int wn = (wid & 1) * 64;
    const int a_row = lane & 15;
    const int a_ko  = lane >> 4;
    const int b_row = (lane & 7) + ((lane & 16) >> 1);
    const int b_ko  = (lane >> 3) & 1;

    const uint32_t aoff = (uint32_t)((a_ko*1024 + (wm + a_row)*8) * 2);
    const uint32_t boff = (uint32_t)((b_ko*1024 + (wn + b_row)*8) * 2);

    float acc[4][8][4];
    #pragma unroll
    for (int i = 0; i < 4; i++)
        #pragma unroll
        for (int j = 0; j < 8; j++)
            #pragma unroll
            for (int e = 0; e < 4; e++) acc[i][j][e] = 0.f;

    const int T = K >> 5;

    load_stage(0, 0);
    if (T > 1) load_stage(1, 1);

    for (int kt = 0; kt < T; kt++) {
        if (kt + 1 < T) cp_wait1(); else cp_wait0();
        __syncthreads();
        if (kt + 2 < T) load_stage(kt + 2, (kt + 2) % 3);

        const uint32_t sb = smem_u32 + (uint32_t)(kt % 3) * STAGE_BYTES;
        #pragma unroll
        for (int ko0 = 0; ko0 < 4; ko0 += 2) {
            uint32_t a_h[4][4], a_l[4][4], b_h[16], b_l[16];
            #pragma unroll
            for (int mf = 0; mf < 4; mf++) {
                const uint32_t ad = sb + aoff + (uint32_t)ko0*2048 + (uint32_t)mf*256;
                ldsm4(a_h[mf], ad);
                ldsm4(a_l[mf], ad + 8192);
            }
            #pragma unroll
            for (int nf2 = 0; nf2 < 4; nf2++) {
                const uint32_t bd = sb + 16384 + boff + (uint32_t)ko0*2048 + (uint32_t)nf2*256;
                ldsm4(&b_h[nf2*4], bd);
                ldsm4(&b_l[nf2*4], bd + 8192);
            }
            #pragma unroll
            for (int mf = 0; mf < 4; mf++)
                #pragma unroll
                for (int nf = 0; nf < 8; nf++) {
                    mma16816(acc[mf][nf], a_h[mf], b_h[nf*2], b_h[nf*2+1]);
                    mma16816(acc[mf][nf], a_h[mf], b_l[nf*2], b_l[nf*2+1]);
                    mma16816(acc[mf][nf], a_l[mf], b_h[nf*2], b_h[nf*2+1]);
                }
        }
        __syncthreads();
    }

    const int er = lane >> 2;
    const int ec = (lane & 3) * 2;
    #pragma unroll
    for (int mf = 0; mf < 4; mf++) {
        #pragma unroll
        for (int nf = 0; nf < 8; nf++) {
            const int m = m0 + wm + mf*16 + er;
            const int n = n0 + wn + nf*8 + ec;
            const float2 bv = *(const float2*)(bias + n);
            #pragma unroll
            for (int half = 0; half < 2; half++) {
                const int mm = m + half*8;
                float t0 = acc[mf][nf][half*2+0] + bv.x;
                float t1 = acc[mf][nf][half*2+1] + bv.y;
                if (EPI == 1) {
                    t0 = 0.5f * t0 * (1.f + erff(t0 * 0.70710678118654752f));
                    t1 = 0.5f * t1 * (1.f + erff(t1 * 0.70710678118654752f));
                }
                if (EPI == 2) {
                    const float2 rv = *(const float2*)(Res + (size_t)mm * N + n);
                    t0 += rv.x; t1 += rv.y;
                }
                if (OF32) {
                    *(float2*)(C + (size_t)mm * N + n) = make_float2(t0, t1);
                }
                if (OSPLIT) {
                    __nv_bfloat16 h0,h1,l0,l1;
                    split1(t0,h0,l0); split1(t1,h1,l1);
                    *(uint32_t*)(Chi + (size_t)mm * N + n) = pack2(h0,h1);
                    *(uint32_t*)(Clo + (size_t)mm * N + n) = pack2(l0,l1);
                }
            }
        }
    }
}

// ---------------------------------------------------------------------------
// Tensor-core full attention (bf16x3 flash).
// Q staged through stage-0 smem then register-resident; smem = 2x32KB = 64KB
// so 3 CTAs/SM (was 80KB / 2 CTAs/SM). Loop body identical to round 4/6.
// ---------------------------------------------------------------------------
#define ATTN_TC_SMEM 65536

__global__ __launch_bounds__(128, 3)
void attn_tc_kernel(const __nv_bfloat16* __restrict__ qkvh,
                    const __nv_bfloat16* __restrict__ qkvl,
                    __nv_bfloat16* __restrict__ oh,
                    __nv_bfloat16* __restrict__ ol)
{
    extern __shared__ char smc[];
    const uint32_t sb = (uint32_t)__cvta_generic_to_shared(smc);

    const int bh = blockIdx.x;
    const int b  = bh >> 4;
    const int h  = bh & 15;
    const int qt = blockIdx.y;
    const int tid  = threadIdx.x;
    const int wid  = tid >> 5;
    const int lane = tid & 31;

    const int r    = tid >> 1;
    const int koh  = (tid & 1) * 4;

    // ---- Phase 1: stage Q through stage-0 smem, then ldsm to registers ----
    {
        const size_t qrow = (size_t)(b*SLEN + qt*64 + r) * D3 + h*HD;
        #pragma unroll
        for (int it = 0; it < 4; it++) {
            const int ko = koh + it;
            const uint32_t dst = sb + (uint32_t)(((ko*64 + r)*8) * 2);
            cp16(dst,        qkvh + qrow + ko*8);
            cp16(dst + 8192, qkvl + qrow + ko*8);
        }
        cp_commit();
    }

    const int a_row = lane & 15;
    const int a_ko  = lane >> 4;
    const int b_row = (lane & 7) + ((lane & 16) >> 1);
    const int b_ko  = (lane >> 3) & 1;
    const int v_key = lane & 15;
    const int v_ko  = lane >> 4;

    uint32_t qa_h[4][4], qa_l[4][4];

    cp_wait0();
    __syncthreads();
    #pragma unroll
    for (int ks = 0; ks < 4; ks++) {
        const uint32_t ad = sb +
            (uint32_t)((((ks*2 + a_ko)*64 + wid*16 + a_row)*8) * 2);
        ldsm4(qa_h[ks], ad);
        ldsm4(qa_l[ks], ad + 8192);
    }
    __syncthreads();   // all warps done reading Q before stage0 is overwritten

    // ---- Phase 2: KV pipeline (2 stages x 32KB) ----
    auto load_kv = [&](int kt, int s) {
        const uint32_t stg = sb + (uint32_t)s * 32768;
        const size_t krow = (size_t)(b*SLEN + kt*64 + r) * D3 + DDIM + h*HD;
        const size_t vrow = krow + DDIM;
        #pragma unroll
        for (int it = 0; it < 4; it++) {
            const int ko = koh + it;
            const uint32_t off = (uint32_t)(((ko*64 + r)*8) * 2);
            cp16(stg + off,          qkvh + krow + ko*8);
            cp16(stg + 8192  + off,  qkvl + krow + ko*8);
            cp16(stg + 16384 + off,  qkvh + vrow + ko*8);
            cp16(stg + 24576 + off,  qkvl + vrow + ko*8);
        }
    };

    load_kv(0, 0);
    cp_commit();

    float m0 = -1e30f, m1 = -1e30f, l0 = 0.f, l1 = 0.f;
    float oacc[8][4];
    #pragma unroll
    for (int nf = 0; nf < 8; nf++)
        #pragma unroll
        for (int e = 0; e < 4; e++) oacc[nf][e] = 0.f;

    for (int kt = 0; kt < 16; kt++) {
        const int s = kt & 1;
        if (kt + 1 < 16) {
            load_kv(kt + 1, s ^ 1);
            cp_commit();
            cp_wait1();
        } else {
            cp_wait0();
        }
        __syncthreads();

        const uint32_t stg = sb + (uint32_t)s * 32768;

        float sc[8][4];
        #pragma unroll
        for (int nf = 0; nf < 8; nf++)
            #pragma unroll
            for (int e = 0; e < 4; e++) sc[nf][e] = 0.f;

        #pragma unroll
        for (int ks = 0; ks < 4; ks++) {
            #pragma unroll
            for (int np = 0; np < 4; np++) {
                uint32_t kb[4], kl[4];
                const uint32_t kd = stg +
                    (uint32_t)((((ks*2 + b_ko)*64 + np*16 + b_row)*8) * 2);
                ldsm4(kb, kd);
                ldsm4(kl, kd + 8192);
                mma16816(sc[2*np],   qa_h[ks], kb[0], kb[1]);
                mma16816(sc[2*np],   qa_h[ks], kl[0], kl[1]);
                mma16816(sc[2*np],   qa_l[ks], kb[0], kb[1]);
                mma16816(sc[2*np+1], qa_h[ks], kb[2], kb[3]);
                mma16816(sc[2*np+1], qa_h[ks], kl[2], kl[3]);
                mma16816(sc[2*np+1], qa_l[ks], kb[2], kb[3]);
            }
        }

        #pragma unroll
        for (int nf = 0; nf < 8; nf++)
            #pragma unroll
            for (int e = 0; e < 4; e++) sc[nf][e] *= 0.125f;

        float mx0 = m0, mx1 = m1;
        #pragma unroll
        for (int nf = 0; nf < 8; nf++) {
            mx0 = fmaxf(mx0, fmaxf(sc[nf][0], sc[nf][1]));
            mx1 = fmaxf(mx1, fmaxf(sc[nf][2], sc[nf][3]));
        }
        mx0 = fmaxf(mx0, __shfl_xor_sync(0xffffffffu, mx0, 1));
        mx0 = fmaxf(mx0, __shfl_xor_sync(0xffffffffu, mx0, 2));
        mx1 = fmaxf(mx1, __shfl_xor_sync(0xffffffffu, mx1, 1));
        mx1 = fmaxf(mx1, __shfl_xor_sync(0xffffffffu, mx1, 2));

        const float al0 = __expf(m0 - mx0);
        const float al1 = __expf(m1 - mx1);
        m0 = mx0; m1 = mx1;

        float s0 = 0.f, s1 = 0.f;
        uint32_t pah[4][4], pal[4][4];
        #pragma unroll
        for (int nf = 0; nf < 8; nf++) {
            const float p0 = __expf(sc[nf][0] - m0);
            const float p1 = __expf(sc[nf][1] - m0);
            const float p2 = __expf(sc[nf][2] - m1);
            const float p3 = __expf(sc[nf][3] - m1);
            s0 += p0 + p1;
            s1 += p2 + p3;
            __nv_bfloat16 h0,h1,h2,h3,lo0,lo1,lo2,lo3;
            split1(p0,h0,lo0); split1(p1,h1,lo1);
            split1(p2,h2,lo2); split1(p3,h3,lo3);
            const int ks = nf >> 1;
            const int hv = (nf & 1) * 2;
            pah[ks][hv+0] = pack2(h0, h1);
            pah[ks][hv+1] = pack2(h2, h3);
            pal[ks][hv+0] = pack2(lo0, lo1);
            pal[ks][hv+1] = pack2(lo2, lo3);
        }
        s0 += __shfl_xor_sync(0xffffffffu, s0, 1);
        s0 += __shfl_xor_sync(0xffffffffu, s0, 2);
        s1 += __shfl_xor_sync(0xffffffffu, s1, 1);
        s1 += __shfl_xor_sync(0xffffffffu, s1, 2);
        l0 = l0 * al0 + s0;
        l1 = l1 * al1 + s1;

        #pragma unroll
        for (int nf = 0; nf < 8; nf++) {
            oacc[nf][0] *= al0; oacc[nf][1] *= al0;
            oacc[nf][2] *= al1; oacc[nf][3] *= al1;
        }

        #pragma unroll
        for (int ks = 0; ks < 4; ks++) {
            #pragma unroll
            for (int np = 0; np < 4; np++) {
                uint32_t vb[4], vl[4];
                const uint32_t vd = stg + 16384 +
                    (uint32_t)((((np*2 + v_ko)*64 + ks*16 + v_key)*8) * 2);
                ldsm4t(vb, vd);
                ldsm4t(vl, vd + 8192);
                mma16816(oacc[2*np],   pah[ks], vb[0], vb[1]);
                mma16816(oacc[2*np],   pah[ks], vl[0], vl[1]);
                mma16816(oacc[2*np],   pal[ks], vb[0], vb[1]);
                mma16816(oacc[2*np+1], pah[ks], vb[2], vb[3]);
                mma16816(oacc[2*np+1], pah[ks], vl[2], vl[3]);
                mma16816(oacc[2*np+1], pal[ks], vb[2], vb[3]);
            }
        }
        __syncthreads();
    }

    const float inv0 = 1.f / l0;
    const float inv1 = 1.f / l1;
    const int er  = lane >> 2;
    const int ec  = (lane & 3) * 2;
    const int tok0 = b*SLEN + qt*64 + wid*16 + er;
    const int tok1 = tok0 + 8;
    #pragma unroll
    for (int nf = 0; nf < 8; nf++) {
        const int col = h*HD + nf*8 + ec;
        const float o0 = oacc[nf][0] * inv0;
        const float o1 = oacc[nf][1] * inv0;
        const float o2 = oacc[nf][2] * inv1;
        const float o3 = oacc[nf][3] * inv1;
        __nv_bfloat16 h0,h1,h2,h3,lo0,lo1,lo2,lo3;
        split1(o0,h0,lo0); split1(o1,h1,lo1);
        split1(o2,h2,lo2); split1(o3,h3,lo3);
        *(uint32_t*)(oh + (size_t)tok0 * DDIM + col) = pack2(h0, h1);
        *(uint32_t*)(ol + (size_t)tok0 * DDIM + col) = pack2(lo0, lo1);
        *(uint32_t*)(oh + (size_t)tok1 * DDIM + col) = pack2(h2, h3);
        *(uint32_t*)(ol + (size_t)tok1 * DDIM + col) = pack2(lo2, lo3);
    }
}

// ---------------------------------------------------------------------------
// Banded attention — unchanged.
// ---------------------------------------------------------------------------
__global__ __launch_bounds__(256)
void attn_band_kernel(const __nv_bfloat16* __restrict__ qkvh,
                      const __nv_bfloat16* __restrict__ qkvl,
                      __nv_bfloat16* __restrict__ oh,
                      __nv_bfloat16* __restrict__ ol)
{
    const int gw   = (blockIdx.x * blockDim.x + threadIdx.x) >> 5;
    const int lane = threadIdx.x & 31;
    const int i = gw & (SLEN-1);
    const int h = (gw >> 10) & (HNUM-1);
    const int b = gw >> 14;

    const size_t qbase = (size_t)(b*SLEN + i) * D3 + h*HD;
    const float q0 = bf2f(qkvh[qbase + lane])      + bf2f(qkvl[qbase + lane]);
    const float q1 = bf2f(qkvh[qbase + 32 + lane]) + bf2f(qkvl[qbase + 32 + lane]);

    float sc[5];
    int   jc[5];
    #pragma unroll
    for (int jj = 0; jj < 5; jj++) {
        int j = i - 2 + jj;
        bool valid = (j >= 0) && (j < SLEN);
        jc[jj] = valid ? j : i;
        const size_t kb = (size_t)(b*SLEN + jc[jj]) * D3 + DDIM + h*HD;
        const float k0 = bf2f(qkvh[kb + lane])      + bf2f(qkvl[kb + lane]);
        const float k1 = bf2f(qkvh[kb + 32 + lane]) + bf2f(qkvl[kb + 32 + lane]);
        float p = q0 * k0 + q1 * k1;
        #pragma unroll
        for (int off = 16; off; off >>= 1) p += __shfl_xor_sync(0xffffffffu, p, off);
        sc[jj] = valid ? p * 0.125f : -1e30f;
    }
    float mx = sc[0];
    #pragma unroll
    for (int jj = 1; jj < 5; jj++) mx = fmaxf(mx, sc[jj]);
    float w[5], sum = 0.f;
    #pragma unroll
    for (int jj = 0; jj < 5; jj++) { w[jj] = __expf(sc[jj] - mx); sum += w[jj]; }
    const float inv = 1.f / sum;

    float o0 = 0.f, o1 = 0.f;
    #pragma unroll
    for (int jj = 0; jj < 5; jj++) {
        const size_t vb = (size_t)(b*SLEN + jc[jj]) * D3 + 2*DDIM + h*HD;
        const float v0 = bf2f(qkvh[vb + lane])      + bf2f(qkvl[vb + lane]);
        const float v1 = bf2f(qkvh[vb + 32 + lane]) + bf2f(qkvl[vb + 32 + lane]);
        o0 = fmaf(w[jj], v0, o0);
        o1 = fmaf(w[jj], v1, o1);
    }
    o0 *= inv; o1 *= inv;

    const size_t ob = (size_t)(b*SLEN + i) * DDIM + h*HD;
    __nv_bfloat16 hh, ll;
    split1(o0, hh, ll);
    oh[ob + lane] = hh;  ol[ob + lane] = ll;
    split1(o1, hh, ll);
    oh[ob + 32 + lane] = hh;  ol[ob + 32 + lane] = ll;
}

// ---------------------------------------------------------------------------
// LayerNorm — unchanged.
// ---------------------------------------------------------------------------
__global__ __launch_bounds__(256)
void ln_kernel(const float* __restrict__ a, const float* __restrict__ r,
               const float* __restrict__ g, const float* __restrict__ bt,
               float* __restrict__ out,
               __nv_bfloat16* __restrict__ ohh, __nv_bfloat16* __restrict__ oll)
{
    __shared__ float red[2][8];
    __shared__ float s_mean, s_rstd;
    const int n = blockIdx.x;
    const int tid = threadIdx.x;
    const size_t base = (size_t)n * DDIM + tid * 4;

    float4 va = *(const float4*)(a + base);
    if (r) {
        float4 vr = *(const float4*)(r + base);
        va.x += vr.x; va.y += vr.y; va.z += vr.z; va.w += vr.w;
    }
    float s  = va.x + va.y + va.z + va.w;
    float sq = va.x*va.x + va.y*va.y + va.z*va.z + va.w*va.w;

    #pragma unroll
    for (int off = 16; off; off >>= 1) {
        s  += __shfl_xor_sync(0xffffffffu, s,  off);
        sq += __shfl_xor_sync(0xffffffffu, sq, off);
    }
    const int wid = tid >> 5;
    if ((tid & 31) == 0) { red[0][wid] = s; red[1][wid] = sq; }
    __syncthreads();
    if (tid < 32) {
        float ts  = (tid < 8) ? red[0][tid] : 0.f;
        float tsq = (tid < 8) ? red[1][tid] : 0.f;
        #pragma unroll
        for (int off = 4; off; off >>= 1) {
            ts  += __shfl_xor_sync(0xffffffffu, ts,  off);
            tsq += __shfl_xor_sync(0xffffffffu, tsq, off);
        }
        if (tid == 0) {
            float mean = ts * (1.f / DDIM);
            float var  = tsq * (1.f / DDIM) - mean * mean;
            s_mean = mean;
            s_rstd = rsqrtf(var + EPS);
        }
    }
    __syncthreads();
    const float mean = s_mean, rstd = s_rstd;
    float4 gg = *(const float4*)(g + tid*4);
    float4 bb = *(const float4*)(bt + tid*4);
    float4 o;
    o.x = (va.x - mean) * rstd * gg.x + bb.x;
    o.y = (va.y - mean) * rstd * gg.y + bb.y;
    o.z = (va.z - mean) * rstd * gg.z + bb.z;
    o.w = (va.w - mean) * rstd * gg.w + bb.w;
    *(float4*)(out + base) = o;
    if (ohh) {
        __nv_bfloat16 h0,h1,h2,h3,l0,l1,l2,l3;
        split1(o.x,h0,l0); split1(o.y,h1,l1); split1(o.z,h2,l2); split1(o.w,h3,l3);
        uint2 uh; uh.x = pack2(h0,h1); uh.y = pack2(h2,h3);
        uint2 ul; ul.x = pack2(l0,l1); ul.y = pack2(l2,l3);
        *(uint2*)(ohh + base) = uh;
        *(uint2*)(oll + base) = ul;
    }
}

// ---------------------------------------------------------------------------
// Orchestration
// ---------------------------------------------------------------------------
extern "C" void kernel_launch(void* const* d_in, const int* in_sizes, int n_in,
                              void* d_out, int out_size)
{
    const float* x_in   = (const float*)d_in[0];
    const float* w_in1  = (const float*)d_in[1];
    const float* b_in1  = (const float*)d_in[2];
    const float* w_out1 = (const float*)d_in[3];
    const float* b_out1 = (const float*)d_in[4];
    const float* ln1_g  = (const float*)d_in[5];
    const float* ln1_b  = (const float*)d_in[6];
    const float* w_in2  = (const float*)d_in[7];
    const float* b_in2  = (const float*)d_in[8];
    const float* w_out2 = (const float*)d_in[9];
    const float* b_out2 = (const float*)d_in[10];
    const float* ln2_g  = (const float*)d_in[11];
    const float* ln2_b  = (const float*)d_in[12];
    const float* ffn_w1 = (const float*)d_in[13];
    const float* ffn_b1 = (const float*)d_in[14];
    const float* ffn_w2 = (const float*)d_in[15];
    const float* ffn_b2 = (const float*)d_in[16];
    const float* lnf_g  = (const float*)d_in[17];
    const float* lnf_b  = (const float*)d_in[18];

    float *PROJ, *X, *X2, *ATT;
    __nv_bfloat16 *WH, *WL, *QKVH, *QKVL, *P1H, *P1L, *P2H, *P2L;
    cudaGetSymbolAddress((void**)&PROJ, g_proj);
    cudaGetSymbolAddress((void**)&X,    g_x);
    cudaGetSymbolAddress((void**)&X2,   g_x2);
    cudaGetSymbolAddress((void**)&ATT,  g_att);
    cudaGetSymbolAddress((void**)&WH,   g_wh);
    cudaGetSymbolAddress((void**)&WL,   g_wl);
    cudaGetSymbolAddress((void**)&QKVH, g_qkvh);
    cudaGetSymbolAddress((void**)&QKVL, g_qkvl);
    cudaGetSymbolAddress((void**)&P1H,  g_p1h);
    cudaGetSymbolAddress((void**)&P1L,  g_p1l);
    cudaGetSymbolAddress((void**)&P2H,  g_p2h);
    cudaGetSymbolAddress((void**)&P2L,  g_p2l);

    cudaFuncSetAttribute(attn_tc_kernel,
                         cudaFuncAttributeMaxDynamicSharedMemorySize, ATTN_TC_SMEM);
    cudaFuncSetAttribute(gemm_bf3<0,false,true>,
                         cudaFuncAttributeMaxDynamicSharedMemorySize, GSMEM_BYTES);
    cudaFuncSetAttribute(gemm_bf3<0,true,false>,
                         cudaFuncAttributeMaxDynamicSharedMemorySize, GSMEM_BYTES);
    cudaFuncSetAttribute(gemm_bf3<1,true,false>,
                         cudaFuncAttributeMaxDynamicSharedMemorySize, GSMEM_BYTES);
    cudaFuncSetAttribute(gemm_bf3<2,true,true>,
                         cudaFuncAttributeMaxDynamicSharedMemorySize, GSMEM_BYTES);

    const dim3 blk(256);
    const dim3 gblk(128);
    const dim3 g_qkvp(D3/128,  NTOK/128);   // (24,16)
    const dim3 g_outp(DDIM/128, NTOK/128);  // (8,16)
    const dim3 g_ffn1(MDIM/128, NTOK/128);  // (32,16)
    const dim3 g_attn(BNUM*HNUM, SLEN/64);  // (32,16)
    const int  g_band = (BNUM*HNUM*SLEN*32) / 256;
    const int  g_ln   = NTOK;

    // ---- weight splits (graph-captured; run every replay). 4096 elems/block ----
    split_kernel<<<(W_OUT1_OFF-W_IN1_OFF)/4096, blk>>>(w_in1,  WH+W_IN1_OFF,  WL+W_IN1_OFF);
    split_kernel<<<(W_IN2_OFF-W_OUT1_OFF)/4096, blk>>>(w_out1, WH+W_OUT1_OFF, WL+W_OUT1_OFF);
    split_kernel<<<(W_OUT2_OFF-W_IN2_OFF)/4096, blk>>>(w_in2,  WH+W_IN2_OFF,  WL+W_IN2_OFF);
    split_kernel<<<(FW1_OFF-W_OUT2_OFF)/4096, blk>>>(w_out2, WH+W_OUT2_OFF, WL+W_OUT2_OFF);
    split_kernel<<<(FW2_OFF-FW1_OFF)/4096, blk>>>(ffn_w1, WH+FW1_OFF,    WL+FW1_OFF);
    split_kernel<<<(WTOTAL-FW2_OFF)/4096, blk>>>(ffn_w2, WH+FW2_OFF,    WL+FW2_OFF);

    // initial activation split (layer-0 input)
    split_kernel<<<(NTOK*DDIM)/4096, blk>>>(x_in, P1H, P1L);

    const float* xcur = x_in;
    for (int l = 0; l < LNUM; l++) {
        const size_t oW3 = (size_t)l * D3 * DDIM;
        const size_t oW1 = (size_t)l * DDIM * DDIM;
        const size_t oWm = (size_t)l * MDIM * DDIM;

        // ---- intra-frame full MHA ----
        gemm_bf3<0,true,false><<<g_qkvp, gblk, GSMEM_BYTES>>>(
            P1H, P1L, WH+W_IN1_OFF+oW3, WL+W_IN1_OFF+oW3,
            b_in1 + (size_t)l*D3, nullptr, nullptr, QKVH, QKVL, NTOK, D3, DDIM);
        attn_tc_kernel<<<g_attn, 128, ATTN_TC_SMEM>>>(QKVH, QKVL, P1H, P1L);
        gemm_bf3<0,false,true><<<g_outp, gblk, GSMEM_BYTES>>>(
            P1H, P1L, WH+W_OUT1_OFF+oW1, WL+W_OUT1_OFF+oW1,
            b_out1 + (size_t)l*DDIM, nullptr, PROJ, nullptr, nullptr, NTOK, DDIM, DDIM);
        ln_kernel<<<g_ln, blk>>>(PROJ, xcur, ln1_g + (size_t)l*DDIM,
                                 ln1_b + (size_t)l*DDIM, X2, P1H, P1L);

        // ---- inter-frame banded MHA ----
        gemm_bf3<0,true,false><<<g_qkvp, gblk, GSMEM_BYTES>>>(
            P1H, P1L, WH+W_IN2_OFF+oW3, WL+W_IN2_OFF+oW3,
            b_in2 + (size_t)l*D3, nullptr, nullptr, QKVH, QKVL, NTOK, D3, DDIM);
        attn_band_kernel<<<g_band, blk>>>(QKVH, QKVL, P1H, P1L);
        gemm_bf3<0,false,true><<<g_outp, gblk, GSMEM_BYTES>>>(
            P1H, P1L, WH+W_OUT2_OFF+oW1, WL+W_OUT2_OFF+oW1,
            b_out2 + (size_t)l*DDIM, nullptr, PROJ, nullptr, nullptr, NTOK, DDIM, DDIM);
        ln_kernel<<<g_ln, blk>>>(PROJ, X2, ln2_g + (size_t)l*DDIM,
                                 ln2_b + (size_t)l*DDIM, ATT, P1H, P1L);

        // ---- FFN ----
        gemm_bf3<1,true,false><<<g_ffn1, gblk, GSMEM_BYTES>>>(
            P1H, P1L, WH+FW1_OFF+oWm, WL+FW1_OFF+oWm,
            ffn_b1 + (size_t)l*MDIM, nullptr, nullptr, P2H, P2L, NTOK, MDIM, DDIM);
        gemm_bf3<2,true,true><<<g_outp, gblk, GSMEM_BYTES>>>(
            P2H, P2L, WH+FW2_OFF+oWm, WL+FW2_OFF+oWm,
            ffn_b2 + (size_t)l*DDIM, ATT, X, P1H, P1L, NTOK, DDIM, MDIM);
        xcur = X;
    }

    ln_kernel<<<g_ln, blk>>>(xcur, nullptr, lnf_g, lnf_b, (float*)d_out,
                             nullptr, nullptr);
}